// round 7
// baseline (speedup 1.0000x reference)
#include <cuda_runtime.h>
#include <cuda_fp16.h>

#define N_NODES 100000
#define N_EDGES 1600000
#define F 64
#define NUM_GRAPHS 64
#define TOPO_DIM 16
#define NUM_CLASSES 4

#define SCAN_BLK 512
#define SCAN_NBLK ((N_NODES + SCAN_BLK - 1) / SCAN_BLK)   // 196

// Scratch (device globals; allocation-free per harness rules)
__device__ int    g_cnt[N_NODES];
__device__ int    g_rowptr[N_NODES];
__device__ int    g_fill[N_NODES];
__device__ int    g_srcs[N_EDGES];
__device__ int    g_lscan[N_NODES];
__device__ int    g_bsum[SCAN_NBLK];
__device__ int    g_boff[SCAN_NBLK];
__device__ float  g_dis[N_NODES];
__device__ __half g_bufA[N_NODES * F];   // xs (fp16) — the gathered buffer
__device__ float  g_bufB[N_NODES * F];   // agg1 (fp32)
__device__ float  g_gsum[NUM_GRAPHS * F];
__device__ float  g_gcnt[NUM_GRAPHS];

// ---------------- init ----------------
__global__ void k_init() {
    int i = blockIdx.x * blockDim.x + threadIdx.x;
    if (i < N_NODES) g_cnt[i] = 0;
    if (i < NUM_GRAPHS * F) g_gsum[i] = 0.0f;
    if (i < NUM_GRAPHS) g_gcnt[i] = 0.0f;
}

// ---------------- degree histogram ----------------
__global__ void k_degree(const int* __restrict__ edge) {
    int e = blockIdx.x * blockDim.x + threadIdx.x;
    if (e < N_EDGES) atomicAdd(&g_cnt[edge[N_EDGES + e]], 1);
}

// ---------------- scan1 + dis + graph counts ----------------
__global__ void k_scan1(const int* __restrict__ batch) {
    __shared__ int s[SCAN_BLK];
    int t = threadIdx.x;
    int i = blockIdx.x * SCAN_BLK + t;
    int v = (i < N_NODES) ? g_cnt[i] : 0;
    if (i < N_NODES) {
        g_dis[i] = rsqrtf((float)v + 1.0f);
        atomicAdd(&g_gcnt[batch[i]], 1.0f);
    }
    s[t] = v;
    __syncthreads();
    #pragma unroll
    for (int off = 1; off < SCAN_BLK; off <<= 1) {
        int add = (t >= off) ? s[t - off] : 0;
        __syncthreads();
        s[t] += add;
        __syncthreads();
    }
    if (i < N_NODES) g_lscan[i] = s[t] - v;
    if (t == SCAN_BLK - 1) g_bsum[blockIdx.x] = s[t];
}

__global__ void k_scan2() {
    __shared__ int s[256];
    int t = threadIdx.x;
    int v = (t < SCAN_NBLK) ? g_bsum[t] : 0;
    s[t] = v;
    __syncthreads();
    #pragma unroll
    for (int off = 1; off < 256; off <<= 1) {
        int add = (t >= off) ? s[t - off] : 0;
        __syncthreads();
        s[t] += add;
        __syncthreads();
    }
    if (t < SCAN_NBLK) g_boff[t] = s[t] - v;
}

__global__ void k_scan3() {
    int i = blockIdx.x * blockDim.x + threadIdx.x;
    if (i < N_NODES) {
        int rp = g_lscan[i] + g_boff[i / SCAN_BLK];
        g_rowptr[i] = rp;
        g_fill[i] = rp;
    }
}

// ---------------- bin edges by dst ----------------
__global__ void k_bin(const int* __restrict__ edge) {
    int e = blockIdx.x * blockDim.x + threadIdx.x;
    if (e < N_EDGES) {
        int src = edge[e];
        int dst = edge[N_EDGES + e];
        int pos = atomicAdd(&g_fill[dst], 1);
        g_srcs[pos] = src;
    }
}

// ---------------- helpers ----------------
// 256-bit global load (sm_100+): 8 b32 regs = 16 halfs
__device__ __forceinline__ void ldg_v8(const void* p, float* r) {
    asm volatile("ld.global.nc.v8.f32 {%0,%1,%2,%3,%4,%5,%6,%7}, [%8];"
        : "=f"(r[0]), "=f"(r[1]), "=f"(r[2]), "=f"(r[3]),
          "=f"(r[4]), "=f"(r[5]), "=f"(r[6]), "=f"(r[7])
        : "l"(p));
}

__device__ __forceinline__ void acc_h16(float* acc, const float* r) {
    #pragma unroll
    for (int k = 0; k < 8; k++) {
        unsigned u = __float_as_uint(r[k]);
        float2 f = __half22float2(*(__half2*)&u);
        acc[2 * k]     += f.x;
        acc[2 * k + 1] += f.y;
    }
}

__device__ __forceinline__ void red_v4(float* p, float a, float b, float c, float d) {
    unsigned long long ga;
    asm("cvta.to.global.u64 %0, %1;" : "=l"(ga) : "l"(p));
    asm volatile("red.global.add.v4.f32 [%0], {%1,%2,%3,%4};"
                 :: "l"(ga), "f"(a), "f"(b), "f"(c), "f"(d) : "memory");
}

// ---------------- GEMM1: xs = (x @ W1) * dis -> fp16 ----------------
__global__ void k_gemm1(const float* __restrict__ x, const float* __restrict__ W) {
    __shared__ float Ws[F * F];
    __shared__ float Xs[64 * F];
    int tid = threadIdx.x;
    float4* Wv = (float4*)Ws;
    const float4* Wg = (const float4*)W;
    #pragma unroll
    for (int i = 0; i < 4; i++) Wv[tid + 256 * i] = Wg[tid + 256 * i];
    int base = blockIdx.x * 64;
    #pragma unroll
    for (int i = 0; i < 4; i++) {
        int idx = tid + 256 * i;
        int row = base + (idx >> 4);
        ((float4*)Xs)[idx] = (row < N_NODES)
            ? ((const float4*)x)[(long long)row * 16 + (idx & 15)]
            : make_float4(0.f, 0.f, 0.f, 0.f);
    }
    __syncthreads();
    int r4 = tid >> 4, c4 = tid & 15;
    float4 acc[4] = {};
    #pragma unroll
    for (int k = 0; k < F; k++) {
        float4 w = ((float4*)Ws)[k * 16 + c4];
        #pragma unroll
        for (int i = 0; i < 4; i++) {
            float xv = Xs[(r4 * 4 + i) * F + k];
            acc[i].x = fmaf(xv, w.x, acc[i].x);
            acc[i].y = fmaf(xv, w.y, acc[i].y);
            acc[i].z = fmaf(xv, w.z, acc[i].z);
            acc[i].w = fmaf(xv, w.w, acc[i].w);
        }
    }
    #pragma unroll
    for (int i = 0; i < 4; i++) {
        int row = base + r4 * 4 + i;
        if (row < N_NODES) {
            float dis = g_dis[row];
            __half2 ha = __floats2half2_rn(acc[i].x * dis, acc[i].y * dis);
            __half2 hb = __floats2half2_rn(acc[i].z * dis, acc[i].w * dis);
            uint2 u; *(__half2*)&u.x = ha; *(__half2*)&u.y = hb;
            ((uint2*)g_bufA)[row * 16 + c4] = u;
        }
    }
}

// ---------------- agg0: bufB[n] = sum_{src} xs[src]  (4 lanes x 32B v8) ----
__global__ void k_agg0() {
    int t = blockIdx.x * blockDim.x + threadIdx.x;
    int node = t >> 2;
    int lane = t & 3;
    if (node >= N_NODES) return;
    int beg = g_rowptr[node];
    int cnt = g_cnt[node];
    const char* A = (const char*)g_bufA;
    long long loff = (long long)lane * 32;
    float acc[16] = {};
    int i = 0;
    for (; i + 4 <= cnt; i += 4) {
        int s0 = __ldg(&g_srcs[beg + i + 0]);
        int s1 = __ldg(&g_srcs[beg + i + 1]);
        int s2 = __ldg(&g_srcs[beg + i + 2]);
        int s3 = __ldg(&g_srcs[beg + i + 3]);
        float r0[8], r1[8], r2[8], r3[8];
        ldg_v8(A + (long long)s0 * 128 + loff, r0);
        ldg_v8(A + (long long)s1 * 128 + loff, r1);
        ldg_v8(A + (long long)s2 * 128 + loff, r2);
        ldg_v8(A + (long long)s3 * 128 + loff, r3);
        acc_h16(acc, r0); acc_h16(acc, r1);
        acc_h16(acc, r2); acc_h16(acc, r3);
    }
    for (; i < cnt; i++) {
        int s = __ldg(&g_srcs[beg + i]);
        float r[8];
        ldg_v8(A + (long long)s * 128 + loff, r);
        acc_h16(acc, r);
    }
    #pragma unroll
    for (int q = 0; q < 4; q++) {
        float4 v = make_float4(acc[q * 4], acc[q * 4 + 1], acc[q * 4 + 2], acc[q * 4 + 3]);
        ((float4*)g_bufB)[node * 16 + lane * 4 + q] = v;
    }
}

// ---------------- GEMM2 fused: h = relu(dis*(agg+xs)+b1); xs2=(h@W2)*dis -> fp16
__global__ void k_gemm2(const float* __restrict__ W, const float* __restrict__ b1) {
    __shared__ float Ws[F * F];
    __shared__ float Hs[64 * F];
    int tid = threadIdx.x;
    float4* Wv = (float4*)Ws;
    const float4* Wg = (const float4*)W;
    #pragma unroll
    for (int i = 0; i < 4; i++) Wv[tid + 256 * i] = Wg[tid + 256 * i];
    int base = blockIdx.x * 64;
    #pragma unroll
    for (int i = 0; i < 4; i++) {
        int idx = tid + 256 * i;
        int row = base + (idx >> 4);
        int c = idx & 15;
        float4 h = make_float4(0.f, 0.f, 0.f, 0.f);
        if (row < N_NODES) {
            float dis = g_dis[row];
            float4 agg = ((const float4*)g_bufB)[(long long)row * 16 + c];
            uint2 xu = ((const uint2*)g_bufA)[row * 16 + c];
            float2 xa = __half22float2(*(__half2*)&xu.x);
            float2 xb = __half22float2(*(__half2*)&xu.y);
            float4 bb = ((const float4*)b1)[c];
            h.x = fmaxf(dis * (agg.x + xa.x) + bb.x, 0.0f);
            h.y = fmaxf(dis * (agg.y + xa.y) + bb.y, 0.0f);
            h.z = fmaxf(dis * (agg.z + xb.x) + bb.z, 0.0f);
            h.w = fmaxf(dis * (agg.w + xb.y) + bb.w, 0.0f);
        }
        ((float4*)Hs)[idx] = h;
    }
    __syncthreads();
    int r4 = tid >> 4, c4 = tid & 15;
    float4 acc[4] = {};
    #pragma unroll
    for (int k = 0; k < F; k++) {
        float4 w = ((float4*)Ws)[k * 16 + c4];
        #pragma unroll
        for (int i = 0; i < 4; i++) {
            float xv = Hs[(r4 * 4 + i) * F + k];
            acc[i].x = fmaf(xv, w.x, acc[i].x);
            acc[i].y = fmaf(xv, w.y, acc[i].y);
            acc[i].z = fmaf(xv, w.z, acc[i].z);
            acc[i].w = fmaf(xv, w.w, acc[i].w);
        }
    }
    #pragma unroll
    for (int i = 0; i < 4; i++) {
        int row = base + r4 * 4 + i;
        if (row < N_NODES) {
            float dis = g_dis[row];
            __half2 ha = __floats2half2_rn(acc[i].x * dis, acc[i].y * dis);
            __half2 hb = __floats2half2_rn(acc[i].z * dis, acc[i].w * dis);
            uint2 u; *(__half2*)&u.x = ha; *(__half2*)&u.y = hb;
            ((uint2*)g_bufA)[row * 16 + c4] = u;   // xs2 (reads done in phase 1)
        }
    }
}

// ---------------- agg1 fused with relu + mean-pool ----------------
// block = 256 threads = 64 nodes x 4 lanes. grid = 1563.
__global__ void k_agg1(const float* __restrict__ b2, const int* __restrict__ batch) {
    __shared__ float hacc[64 * F];   // 16KB
    int tid = threadIdx.x;
    int s = tid >> 2;                 // node-in-block 0..63
    int lane = tid & 3;
    int base = blockIdx.x * 64;
    int node = base + s;
    const char* A = (const char*)g_bufA;
    long long loff = (long long)lane * 32;
    float h[16];
    #pragma unroll
    for (int j = 0; j < 16; j++) h[j] = 0.0f;

    if (node < N_NODES) {
        int beg = g_rowptr[node];
        int cnt = g_cnt[node];
        float acc[16] = {};
        int i = 0;
        for (; i + 4 <= cnt; i += 4) {
            int s0 = __ldg(&g_srcs[beg + i + 0]);
            int s1 = __ldg(&g_srcs[beg + i + 1]);
            int s2 = __ldg(&g_srcs[beg + i + 2]);
            int s3 = __ldg(&g_srcs[beg + i + 3]);
            float r0[8], r1[8], r2[8], r3[8];
            ldg_v8(A + (long long)s0 * 128 + loff, r0);
            ldg_v8(A + (long long)s1 * 128 + loff, r1);
            ldg_v8(A + (long long)s2 * 128 + loff, r2);
            ldg_v8(A + (long long)s3 * 128 + loff, r3);
            acc_h16(acc, r0); acc_h16(acc, r1);
            acc_h16(acc, r2); acc_h16(acc, r3);
        }
        for (; i < cnt; i++) {
            int sidx = __ldg(&g_srcs[beg + i]);
            float r[8];
            ldg_v8(A + (long long)sidx * 128 + loff, r);
            acc_h16(acc, r);
        }
        // self-loop + bias + relu
        float dis = g_dis[node];
        float xr[8];
        ldg_v8(A + (long long)node * 128 + loff, xr);
        float xs[16];
        #pragma unroll
        for (int k = 0; k < 8; k++) {
            unsigned u = __float_as_uint(xr[k]);
            float2 f = __half22float2(*(__half2*)&u);
            xs[2 * k] = f.x; xs[2 * k + 1] = f.y;
        }
        #pragma unroll
        for (int j = 0; j < 16; j++)
            h[j] = fmaxf(dis * (acc[j] + xs[j]) + b2[lane * 16 + j], 0.0f);
    }
    #pragma unroll
    for (int j = 0; j < 16; j++) hacc[s * F + lane * 16 + j] = h[j];
    __syncthreads();

    int lastnode = base + 63 < N_NODES ? base + 63 : N_NODES - 1;
    int g0 = batch[base < N_NODES ? base : N_NODES - 1];
    int g1 = batch[lastnode];
    if (g0 == g1) {
        // whole block one graph: tree-reduce 64 rows, then 16 red.v4
        #pragma unroll
        for (int off = 32; off >= 1; off >>= 1) {
            if (s < off) {
                #pragma unroll
                for (int j = 0; j < 16; j++)
                    hacc[s * F + lane * 16 + j] += hacc[(s + off) * F + lane * 16 + j];
            }
            __syncthreads();
        }
        if (tid < 16) {
            float4 v = ((float4*)hacc)[tid];
            red_v4(&g_gsum[g0 * F + tid * 4], v.x, v.y, v.z, v.w);
        }
    } else if (node < N_NODES) {
        // boundary block: per-node reductions
        int g = batch[node];
        red_v4(&g_gsum[g * F + lane * 16 + 0],  h[0],  h[1],  h[2],  h[3]);
        red_v4(&g_gsum[g * F + lane * 16 + 4],  h[4],  h[5],  h[6],  h[7]);
        red_v4(&g_gsum[g * F + lane * 16 + 8],  h[8],  h[9],  h[10], h[11]);
        red_v4(&g_gsum[g * F + lane * 16 + 12], h[12], h[13], h[14], h[15]);
    }
}

// ---------------- head ----------------
__global__ void k_head(const float* __restrict__ topo, const float* __restrict__ Wlin,
                       const float* __restrict__ blin, float* __restrict__ out) {
    int t = threadIdx.x;
    int g = t >> 2, c = t & 3;
    float inv = 1.0f / fmaxf(g_gcnt[g], 1.0f);
    float acc = blin[c];
    #pragma unroll
    for (int k = 0; k < F; k++)
        acc = fmaf(g_gsum[g * F + k] * inv, Wlin[k * NUM_CLASSES + c], acc);
    #pragma unroll
    for (int k = 0; k < TOPO_DIM; k++)
        acc = fmaf(topo[g * TOPO_DIM + k], Wlin[(F + k) * NUM_CLASSES + c], acc);
    out[g * NUM_CLASSES + c] = acc;
}

extern "C" void kernel_launch(void* const* d_in, const int* in_sizes, int n_in,
                              void* d_out, int out_size) {
    const float* x    = (const float*)d_in[0];
    const int*   edge = (const int*)d_in[1];
    const int*   batch= (const int*)d_in[2];
    const float* topo = (const float*)d_in[3];
    const float* W1   = (const float*)d_in[4];
    const float* b1   = (const float*)d_in[5];
    const float* W2   = (const float*)d_in[6];
    const float* b2   = (const float*)d_in[7];
    const float* Wlin = (const float*)d_in[8];
    const float* blin = (const float*)d_in[9];
    float* out = (float*)d_out;

    const int gblocks = (N_NODES + 63) / 64;          // 1563
    const int ablocks = (N_NODES * 4 + 255) / 256;    // 1563

    k_init<<<(N_NODES + 255) / 256, 256>>>();
    k_degree<<<(N_EDGES + 255) / 256, 256>>>(edge);
    k_scan1<<<SCAN_NBLK, SCAN_BLK>>>(batch);
    k_scan2<<<1, 256>>>();
    k_scan3<<<(N_NODES + 255) / 256, 256>>>();
    k_bin<<<(N_EDGES + 255) / 256, 256>>>(edge);

    k_gemm1<<<gblocks, 256>>>(x, W1);
    k_agg0<<<ablocks, 256>>>();
    k_gemm2<<<gblocks, 256>>>(W2, b1);
    k_agg1<<<ablocks, 256>>>(b2, batch);
    k_head<<<1, 256>>>(topo, Wlin, blin, out);
}

// round 8
// speedup vs baseline: 1.0647x; 1.0647x over previous
#include <cuda_runtime.h>
#include <cuda_fp16.h>

#define N_NODES 100000
#define N_EDGES 1600000
#define F 64
#define NUM_GRAPHS 64
#define TOPO_DIM 16
#define NUM_CLASSES 4

#define SCAN_BLK 512
#define SCAN_NBLK ((N_NODES + SCAN_BLK - 1) / SCAN_BLK)   // 196

// Scratch (device globals; allocation-free per harness rules)
__device__ int      g_cnt[N_NODES];
__device__ int      g_rowptr[N_NODES];
__device__ int      g_fill[N_NODES];
__device__ int      g_srcs[N_EDGES];
__device__ unsigned g_bpub[SCAN_NBLK];   // decoupled-lookback publish: (sum<<1)|1
__device__ float    g_dis[N_NODES];
__device__ __half   g_bufA[N_NODES * F];   // xs (fp16) — gathered buffer
__device__ __half   g_bufH[N_NODES * F];   // h after layer1 relu (fp16)
__device__ float    g_gsum[NUM_GRAPHS * F];
__device__ float    g_gcnt[NUM_GRAPHS];

// ---------------- init ----------------
__global__ void k_init() {
    int i = blockIdx.x * blockDim.x + threadIdx.x;
    if (i < N_NODES) g_cnt[i] = 0;
    if (i < SCAN_NBLK) g_bpub[i] = 0u;
    if (i < NUM_GRAPHS * F) g_gsum[i] = 0.0f;
    if (i < NUM_GRAPHS) g_gcnt[i] = 0.0f;
}

// ---------------- degree histogram ----------------
__global__ void k_degree(const int* __restrict__ edge) {
    int e = blockIdx.x * blockDim.x + threadIdx.x;
    if (e < N_EDGES) atomicAdd(&g_cnt[edge[N_EDGES + e]], 1);
}

// ---------------- single-launch scan (decoupled lookback) + dis + gcnt ----------
__global__ void k_scan(const int* __restrict__ batch) {
    __shared__ int s[SCAN_BLK];
    __shared__ int s_boff;
    int t = threadIdx.x, b = blockIdx.x;
    int i = b * SCAN_BLK + t;
    int v = (i < N_NODES) ? g_cnt[i] : 0;
    if (i < N_NODES) {
        g_dis[i] = rsqrtf((float)v + 1.0f);
        atomicAdd(&g_gcnt[batch[i]], 1.0f);
    }
    s[t] = v;
    __syncthreads();
    #pragma unroll
    for (int off = 1; off < SCAN_BLK; off <<= 1) {
        int add = (t >= off) ? s[t - off] : 0;
        __syncthreads();
        s[t] += add;
        __syncthreads();
    }
    // publish this block's total BEFORE lookback (deadlock-free; all blocks resident)
    if (t == SCAN_BLK - 1) {
        __threadfence();
        atomicExch(&g_bpub[b], ((unsigned)s[SCAN_BLK - 1] << 1) | 1u);
    }
    // warp 0: parallel lookback over predecessors
    if (t < 32) {
        int sum = 0;
        for (int base = 0; base < b; base += 32) {
            int idx = base + t;
            if (idx < b) {
                unsigned val;
                do { val = atomicOr(&g_bpub[idx], 0u); } while (!(val & 1u));
                sum += (int)(val >> 1);
            }
        }
        #pragma unroll
        for (int off = 16; off; off >>= 1)
            sum += __shfl_down_sync(0xffffffffu, sum, off);
        if (t == 0) s_boff = sum;
    }
    __syncthreads();
    if (i < N_NODES) {
        int rp = s_boff + s[t] - v;   // exclusive
        g_rowptr[i] = rp;
        g_fill[i] = rp;
    }
}

// ---------------- bin edges by dst ----------------
__global__ void k_bin(const int* __restrict__ edge) {
    int e = blockIdx.x * blockDim.x + threadIdx.x;
    if (e < N_EDGES) {
        int src = edge[e];
        int dst = edge[N_EDGES + e];
        int pos = atomicAdd(&g_fill[dst], 1);
        g_srcs[pos] = src;
    }
}

// ---------------- helpers ----------------
__device__ __forceinline__ void acc_half8(float* acc, uint4 u) {
    float2 f;
    f = __half22float2(*(__half2*)&u.x); acc[0] += f.x; acc[1] += f.y;
    f = __half22float2(*(__half2*)&u.y); acc[2] += f.x; acc[3] += f.y;
    f = __half22float2(*(__half2*)&u.z); acc[4] += f.x; acc[5] += f.y;
    f = __half22float2(*(__half2*)&u.w); acc[6] += f.x; acc[7] += f.y;
}

__device__ __forceinline__ void red_v4(float* p, float a, float b, float c, float d) {
    unsigned long long ga;
    asm("cvta.to.global.u64 %0, %1;" : "=l"(ga) : "l"(p));
    asm volatile("red.global.add.v4.f32 [%0], {%1,%2,%3,%4};"
                 :: "l"(ga), "f"(a), "f"(b), "f"(c), "f"(d) : "memory");
}

// ---------------- GEMM1: xs = (x @ W1) * dis -> fp16 bufA ----------------
__global__ void k_gemm1(const float* __restrict__ x, const float* __restrict__ W) {
    __shared__ float Ws[F * F];
    __shared__ float Xs[64 * F];
    int tid = threadIdx.x;
    float4* Wv = (float4*)Ws;
    const float4* Wg = (const float4*)W;
    #pragma unroll
    for (int i = 0; i < 4; i++) Wv[tid + 256 * i] = Wg[tid + 256 * i];
    int base = blockIdx.x * 64;
    #pragma unroll
    for (int i = 0; i < 4; i++) {
        int idx = tid + 256 * i;
        int row = base + (idx >> 4);
        ((float4*)Xs)[idx] = (row < N_NODES)
            ? ((const float4*)x)[(long long)row * 16 + (idx & 15)]
            : make_float4(0.f, 0.f, 0.f, 0.f);
    }
    __syncthreads();
    int r4 = tid >> 4, c4 = tid & 15;
    float4 acc[4] = {};
    #pragma unroll
    for (int k = 0; k < F; k++) {
        float4 w = ((float4*)Ws)[k * 16 + c4];
        #pragma unroll
        for (int i = 0; i < 4; i++) {
            float xv = Xs[(r4 * 4 + i) * F + k];
            acc[i].x = fmaf(xv, w.x, acc[i].x);
            acc[i].y = fmaf(xv, w.y, acc[i].y);
            acc[i].z = fmaf(xv, w.z, acc[i].z);
            acc[i].w = fmaf(xv, w.w, acc[i].w);
        }
    }
    #pragma unroll
    for (int i = 0; i < 4; i++) {
        int row = base + r4 * 4 + i;
        if (row < N_NODES) {
            float dis = g_dis[row];
            __half2 ha = __floats2half2_rn(acc[i].x * dis, acc[i].y * dis);
            __half2 hb = __floats2half2_rn(acc[i].z * dis, acc[i].w * dis);
            uint2 u; *(__half2*)&u.x = ha; *(__half2*)&u.y = hb;
            ((uint2*)g_bufA)[row * 16 + c4] = u;
        }
    }
}

// ---------------- agg0 fused: h = relu(dis*(sum+xs)+b1) -> fp16 bufH ----------
// 8 lanes x 16B per node, unroll-4 MLP. (R6 layout — proven fastest.)
__global__ void k_agg0(const float* __restrict__ b1) {
    int t = blockIdx.x * blockDim.x + threadIdx.x;
    int node = t >> 3;
    int lane = t & 7;
    if (node >= N_NODES) return;
    int beg = g_rowptr[node];
    int cnt = g_cnt[node];
    const uint4* A = (const uint4*)g_bufA;
    float acc[8] = {};
    int i = 0;
    for (; i + 4 <= cnt; i += 4) {
        int s0 = __ldg(&g_srcs[beg + i + 0]);
        int s1 = __ldg(&g_srcs[beg + i + 1]);
        int s2 = __ldg(&g_srcs[beg + i + 2]);
        int s3 = __ldg(&g_srcs[beg + i + 3]);
        uint4 u0 = __ldg(&A[s0 * 8 + lane]);
        uint4 u1 = __ldg(&A[s1 * 8 + lane]);
        uint4 u2 = __ldg(&A[s2 * 8 + lane]);
        uint4 u3 = __ldg(&A[s3 * 8 + lane]);
        acc_half8(acc, u0); acc_half8(acc, u1);
        acc_half8(acc, u2); acc_half8(acc, u3);
    }
    for (; i < cnt; i++) {
        int s = __ldg(&g_srcs[beg + i]);
        acc_half8(acc, __ldg(&A[s * 8 + lane]));
    }
    // self-loop + bias + relu -> fp16 h
    float dis = g_dis[node];
    float xs[8] = {};
    acc_half8(xs, __ldg(&A[node * 8 + lane]));
    uint4 out;
    float h0, h1;
    h0 = fmaxf(dis * (acc[0] + xs[0]) + b1[lane * 8 + 0], 0.0f);
    h1 = fmaxf(dis * (acc[1] + xs[1]) + b1[lane * 8 + 1], 0.0f);
    *(__half2*)&out.x = __floats2half2_rn(h0, h1);
    h0 = fmaxf(dis * (acc[2] + xs[2]) + b1[lane * 8 + 2], 0.0f);
    h1 = fmaxf(dis * (acc[3] + xs[3]) + b1[lane * 8 + 3], 0.0f);
    *(__half2*)&out.y = __floats2half2_rn(h0, h1);
    h0 = fmaxf(dis * (acc[4] + xs[4]) + b1[lane * 8 + 4], 0.0f);
    h1 = fmaxf(dis * (acc[5] + xs[5]) + b1[lane * 8 + 5], 0.0f);
    *(__half2*)&out.z = __floats2half2_rn(h0, h1);
    h0 = fmaxf(dis * (acc[6] + xs[6]) + b1[lane * 8 + 6], 0.0f);
    h1 = fmaxf(dis * (acc[7] + xs[7]) + b1[lane * 8 + 7], 0.0f);
    *(__half2*)&out.w = __floats2half2_rn(h0, h1);
    ((uint4*)g_bufH)[node * 8 + lane] = out;
}

// ---------------- GEMM2: xs2 = (h @ W2) * dis -> fp16 bufA ----------------
__global__ void k_gemm2(const float* __restrict__ W) {
    __shared__ float Ws[F * F];
    __shared__ float Hs[64 * F];
    int tid = threadIdx.x;
    float4* Wv = (float4*)Ws;
    const float4* Wg = (const float4*)W;
    #pragma unroll
    for (int i = 0; i < 4; i++) Wv[tid + 256 * i] = Wg[tid + 256 * i];
    int base = blockIdx.x * 64;
    #pragma unroll
    for (int i = 0; i < 4; i++) {
        int idx = tid + 256 * i;
        int row = base + (idx >> 4);
        int c = idx & 15;
        float4 h = make_float4(0.f, 0.f, 0.f, 0.f);
        if (row < N_NODES) {
            uint2 hu = ((const uint2*)g_bufH)[row * 16 + c];
            float2 ha = __half22float2(*(__half2*)&hu.x);
            float2 hb = __half22float2(*(__half2*)&hu.y);
            h = make_float4(ha.x, ha.y, hb.x, hb.y);
        }
        ((float4*)Hs)[idx] = h;
    }
    __syncthreads();
    int r4 = tid >> 4, c4 = tid & 15;
    float4 acc[4] = {};
    #pragma unroll
    for (int k = 0; k < F; k++) {
        float4 w = ((float4*)Ws)[k * 16 + c4];
        #pragma unroll
        for (int i = 0; i < 4; i++) {
            float xv = Hs[(r4 * 4 + i) * F + k];
            acc[i].x = fmaf(xv, w.x, acc[i].x);
            acc[i].y = fmaf(xv, w.y, acc[i].y);
            acc[i].z = fmaf(xv, w.z, acc[i].z);
            acc[i].w = fmaf(xv, w.w, acc[i].w);
        }
    }
    #pragma unroll
    for (int i = 0; i < 4; i++) {
        int row = base + r4 * 4 + i;
        if (row < N_NODES) {
            float dis = g_dis[row];
            __half2 ha = __floats2half2_rn(acc[i].x * dis, acc[i].y * dis);
            __half2 hb = __floats2half2_rn(acc[i].z * dis, acc[i].w * dis);
            uint2 u; *(__half2*)&u.x = ha; *(__half2*)&u.y = hb;
            ((uint2*)g_bufA)[row * 16 + c4] = u;   // xs2
        }
    }
}

// ---------------- agg1 fused with relu + mean-pool ----------------
// block = 256 threads = 32 nodes x 8 lanes. grid = 3125 exact.
__global__ void k_agg1(const float* __restrict__ b2, const int* __restrict__ batch) {
    __shared__ float hacc[32 * F];   // 8KB
    int tid = threadIdx.x;
    int s = tid >> 3;
    int lane = tid & 7;
    int base = blockIdx.x * 32;
    int node = base + s;
    int beg = g_rowptr[node];
    int cnt = g_cnt[node];
    const uint4* A = (const uint4*)g_bufA;
    float acc[8] = {};
    int i = 0;
    for (; i + 4 <= cnt; i += 4) {
        int s0 = __ldg(&g_srcs[beg + i + 0]);
        int s1 = __ldg(&g_srcs[beg + i + 1]);
        int s2 = __ldg(&g_srcs[beg + i + 2]);
        int s3 = __ldg(&g_srcs[beg + i + 3]);
        uint4 u0 = __ldg(&A[s0 * 8 + lane]);
        uint4 u1 = __ldg(&A[s1 * 8 + lane]);
        uint4 u2 = __ldg(&A[s2 * 8 + lane]);
        uint4 u3 = __ldg(&A[s3 * 8 + lane]);
        acc_half8(acc, u0); acc_half8(acc, u1);
        acc_half8(acc, u2); acc_half8(acc, u3);
    }
    for (; i < cnt; i++) {
        int sidx = __ldg(&g_srcs[beg + i]);
        acc_half8(acc, __ldg(&A[sidx * 8 + lane]));
    }
    float dis = g_dis[node];
    float xs[8] = {};
    acc_half8(xs, __ldg(&A[node * 8 + lane]));
    float h[8];
    #pragma unroll
    for (int j = 0; j < 8; j++)
        h[j] = fmaxf(dis * (acc[j] + xs[j]) + b2[lane * 8 + j], 0.0f);
    #pragma unroll
    for (int j = 0; j < 8; j++) hacc[s * F + lane * 8 + j] = h[j];
    __syncthreads();

    int g0 = batch[base];
    int g1 = batch[base + 31];
    if (g0 == g1) {
        #pragma unroll
        for (int off = 16; off >= 1; off >>= 1) {
            if (s < off) {
                #pragma unroll
                for (int j = 0; j < 8; j++)
                    hacc[s * F + lane * 8 + j] += hacc[(s + off) * F + lane * 8 + j];
            }
            __syncthreads();
        }
        if (tid < 16) {
            float4 v = ((float4*)hacc)[tid];
            red_v4(&g_gsum[g0 * F + tid * 4], v.x, v.y, v.z, v.w);
        }
    } else {
        int g = batch[node];
        red_v4(&g_gsum[g * F + lane * 8 + 0], h[0], h[1], h[2], h[3]);
        red_v4(&g_gsum[g * F + lane * 8 + 4], h[4], h[5], h[6], h[7]);
    }
}

// ---------------- head ----------------
__global__ void k_head(const float* __restrict__ topo, const float* __restrict__ Wlin,
                       const float* __restrict__ blin, float* __restrict__ out) {
    int t = threadIdx.x;
    int g = t >> 2, c = t & 3;
    float inv = 1.0f / fmaxf(g_gcnt[g], 1.0f);
    float acc = blin[c];
    #pragma unroll
    for (int k = 0; k < F; k++)
        acc = fmaf(g_gsum[g * F + k] * inv, Wlin[k * NUM_CLASSES + c], acc);
    #pragma unroll
    for (int k = 0; k < TOPO_DIM; k++)
        acc = fmaf(topo[g * TOPO_DIM + k], Wlin[(F + k) * NUM_CLASSES + c], acc);
    out[g * NUM_CLASSES + c] = acc;
}

extern "C" void kernel_launch(void* const* d_in, const int* in_sizes, int n_in,
                              void* d_out, int out_size) {
    const float* x    = (const float*)d_in[0];
    const int*   edge = (const int*)d_in[1];
    const int*   batch= (const int*)d_in[2];
    const float* topo = (const float*)d_in[3];
    const float* W1   = (const float*)d_in[4];
    const float* b1   = (const float*)d_in[5];
    const float* W2   = (const float*)d_in[6];
    const float* b2   = (const float*)d_in[7];
    const float* Wlin = (const float*)d_in[8];
    const float* blin = (const float*)d_in[9];
    float* out = (float*)d_out;

    const int gblocks = (N_NODES + 63) / 64;          // 1563
    const int ablocks = N_NODES * 8 / 256;            // 3125 exact

    k_init<<<(N_NODES + 255) / 256, 256>>>();                 // 1
    k_degree<<<(N_EDGES + 255) / 256, 256>>>(edge);           // 2
    k_scan<<<SCAN_NBLK, SCAN_BLK>>>(batch);                   // 3
    k_bin<<<(N_EDGES + 255) / 256, 256>>>(edge);              // 4
    k_gemm1<<<gblocks, 256>>>(x, W1);                         // 5
    k_agg0<<<ablocks, 256>>>(b1);                             // 6  <- ncu -s 5 lands here
    k_gemm2<<<gblocks, 256>>>(W2);                            // 7
    k_agg1<<<ablocks, 256>>>(b2, batch);                      // 8
    k_head<<<1, 256>>>(topo, Wlin, blin, out);                // 9
}

// round 9
// speedup vs baseline: 1.0884x; 1.0223x over previous
#include <cuda_runtime.h>
#include <cuda_fp16.h>

#define N_NODES 100000
#define N_EDGES 1600000
#define F 64
#define NUM_GRAPHS 64
#define TOPO_DIM 16
#define NUM_CLASSES 4

#define SCAN_BLK 512
#define SCAN_NBLK ((N_NODES + SCAN_BLK - 1) / SCAN_BLK)   // 196

#define SA 72   // smem row stride (halfs) — conflict-free for frag loads

// Scratch (device globals; allocation-free per harness rules)
__device__ int      g_cnt[N_NODES];
__device__ int      g_rowptr[N_NODES];
__device__ int      g_fill[N_NODES];
__device__ int      g_srcs[N_EDGES];
__device__ unsigned g_bpub[SCAN_NBLK];
__device__ float    g_dis[N_NODES];
__device__ __half   g_bufA[N_NODES * F];   // xs (fp16) — gathered buffer
__device__ __half   g_bufH[N_NODES * F];   // h after layer1 relu (fp16)
__device__ __half   g_W1t[F * F];          // W1 transposed fp16 [n][k]
__device__ __half   g_W2t[F * F];          // W2 transposed fp16 [n][k]
__device__ float    g_gsum[NUM_GRAPHS * F];
__device__ float    g_gcnt[NUM_GRAPHS];

// ---------------- init ----------------
__global__ void k_init() {
    int i = blockIdx.x * blockDim.x + threadIdx.x;
    if (i < N_NODES) g_cnt[i] = 0;
    if (i < SCAN_NBLK) g_bpub[i] = 0u;
    if (i < NUM_GRAPHS * F) g_gsum[i] = 0.0f;
    if (i < NUM_GRAPHS) g_gcnt[i] = 0.0f;
}

// ---------------- weight prep: transpose + fp16 ----------------
__global__ void k_prepW(const float* __restrict__ W1, const float* __restrict__ W2) {
    int t = threadIdx.x;   // 256
    #pragma unroll
    for (int j = 0; j < 16; j++) {
        int e = t + 256 * j;        // 4096
        int k = e >> 6, n = e & 63;
        g_W1t[n * F + k] = __float2half(W1[e]);
        g_W2t[n * F + k] = __float2half(W2[e]);
    }
}

// ---------------- degree histogram (4 edges/thread, MLP=4) ----------------
__global__ void k_degree(const int* __restrict__ edge) {
    int t = blockIdx.x * blockDim.x + threadIdx.x;
    if (t < N_EDGES / 4) {
        int4 d = ((const int4*)(edge + N_EDGES))[t];
        atomicAdd(&g_cnt[d.x], 1);
        atomicAdd(&g_cnt[d.y], 1);
        atomicAdd(&g_cnt[d.z], 1);
        atomicAdd(&g_cnt[d.w], 1);
    }
}

// ---------------- single-launch scan (decoupled lookback) + dis + gcnt ----------
__global__ void k_scan(const int* __restrict__ batch) {
    __shared__ int s[SCAN_BLK];
    __shared__ int s_boff;
    int t = threadIdx.x, b = blockIdx.x;
    int i = b * SCAN_BLK + t;
    int v = (i < N_NODES) ? g_cnt[i] : 0;
    if (i < N_NODES) {
        g_dis[i] = rsqrtf((float)v + 1.0f);
        atomicAdd(&g_gcnt[batch[i]], 1.0f);
    }
    s[t] = v;
    __syncthreads();
    #pragma unroll
    for (int off = 1; off < SCAN_BLK; off <<= 1) {
        int add = (t >= off) ? s[t - off] : 0;
        __syncthreads();
        s[t] += add;
        __syncthreads();
    }
    if (t == SCAN_BLK - 1) {
        __threadfence();
        atomicExch(&g_bpub[b], ((unsigned)s[SCAN_BLK - 1] << 1) | 1u);
    }
    if (t < 32) {
        int sum = 0;
        for (int base = 0; base < b; base += 32) {
            int idx = base + t;
            if (idx < b) {
                unsigned val;
                do { val = atomicOr(&g_bpub[idx], 0u); } while (!(val & 1u));
                sum += (int)(val >> 1);
            }
        }
        #pragma unroll
        for (int off = 16; off; off >>= 1)
            sum += __shfl_down_sync(0xffffffffu, sum, off);
        if (t == 0) s_boff = sum;
    }
    __syncthreads();
    if (i < N_NODES) {
        int rp = s_boff + s[t] - v;
        g_rowptr[i] = rp;
        g_fill[i] = rp;
    }
}

// ---------------- bin edges by dst (4 edges/thread, MLP=4) ----------------
__global__ void k_bin(const int* __restrict__ edge) {
    int t = blockIdx.x * blockDim.x + threadIdx.x;
    if (t < N_EDGES / 4) {
        int4 s = ((const int4*)edge)[t];
        int4 d = ((const int4*)(edge + N_EDGES))[t];
        int p0 = atomicAdd(&g_fill[d.x], 1);
        int p1 = atomicAdd(&g_fill[d.y], 1);
        int p2 = atomicAdd(&g_fill[d.z], 1);
        int p3 = atomicAdd(&g_fill[d.w], 1);
        g_srcs[p0] = s.x;
        g_srcs[p1] = s.y;
        g_srcs[p2] = s.z;
        g_srcs[p3] = s.w;
    }
}

// ---------------- helpers ----------------
__device__ __forceinline__ void acc_half8(float* acc, uint4 u) {
    float2 f;
    f = __half22float2(*(__half2*)&u.x); acc[0] += f.x; acc[1] += f.y;
    f = __half22float2(*(__half2*)&u.y); acc[2] += f.x; acc[3] += f.y;
    f = __half22float2(*(__half2*)&u.z); acc[4] += f.x; acc[5] += f.y;
    f = __half22float2(*(__half2*)&u.w); acc[6] += f.x; acc[7] += f.y;
}

__device__ __forceinline__ void red_v4(float* p, float a, float b, float c, float d) {
    unsigned long long ga;
    asm("cvta.to.global.u64 %0, %1;" : "=l"(ga) : "l"(p));
    asm volatile("red.global.add.v4.f32 [%0], {%1,%2,%3,%4};"
                 :: "l"(ga), "f"(a), "f"(b), "f"(c), "f"(d) : "memory");
}

__device__ __forceinline__ void mma16816(float* c,
    unsigned a0, unsigned a1, unsigned a2, unsigned a3,
    unsigned b0, unsigned b1) {
    asm volatile("mma.sync.aligned.m16n8k16.row.col.f32.f16.f16.f32 "
        "{%0,%1,%2,%3}, {%4,%5,%6,%7}, {%8,%9}, {%0,%1,%2,%3};"
        : "+f"(c[0]), "+f"(c[1]), "+f"(c[2]), "+f"(c[3])
        : "r"(a0), "r"(a1), "r"(a2), "r"(a3), "r"(b0), "r"(b1));
}

// Shared mma mainloop + epilogue: As[64][SA] fp16 staged, Wt smem staged.
// Block = 128 threads (4 warps), warp w handles rows w*16..w*16+15, all 64 cols.
__device__ __forceinline__ void mma_body(const __half* As, const __half* Wt, int base) {
    int lane = threadIdx.x & 31;
    int w = threadIdx.x >> 5;
    int g = lane >> 2, tg = lane & 3;
    int R = w * 16;
    float c[8][4] = {};
    #pragma unroll
    for (int k0 = 0; k0 < F; k0 += 16) {
        unsigned a0 = *(const unsigned*)&As[(R + g) * SA + k0 + tg * 2];
        unsigned a1 = *(const unsigned*)&As[(R + g + 8) * SA + k0 + tg * 2];
        unsigned a2 = *(const unsigned*)&As[(R + g) * SA + k0 + tg * 2 + 8];
        unsigned a3 = *(const unsigned*)&As[(R + g + 8) * SA + k0 + tg * 2 + 8];
        #pragma unroll
        for (int n = 0; n < 8; n++) {
            unsigned b0 = *(const unsigned*)&Wt[(n * 8 + g) * SA + k0 + tg * 2];
            unsigned b1 = *(const unsigned*)&Wt[(n * 8 + g) * SA + k0 + tg * 2 + 8];
            mma16816(c[n], a0, a1, a2, a3, b0, b1);
        }
    }
    // epilogue: scale by dis, fp16, store to bufA
    int row0 = base + R + g;
    int row1 = row0 + 8;
    float dis0 = (row0 < N_NODES) ? g_dis[row0] : 0.0f;
    float dis1 = (row1 < N_NODES) ? g_dis[row1] : 0.0f;
    #pragma unroll
    for (int n = 0; n < 8; n++) {
        int col = n * 8 + tg * 2;
        if (row0 < N_NODES) {
            __half2 h = __floats2half2_rn(c[n][0] * dis0, c[n][1] * dis0);
            *(__half2*)&g_bufA[row0 * F + col] = h;
        }
        if (row1 < N_NODES) {
            __half2 h = __floats2half2_rn(c[n][2] * dis1, c[n][3] * dis1);
            *(__half2*)&g_bufA[row1 * F + col] = h;
        }
    }
}

__device__ __forceinline__ void load_Wt_smem(__half* Wt, const __half* Wg) {
    int t = threadIdx.x;   // 128
    #pragma unroll
    for (int j = 0; j < 4; j++) {
        int idx = t + 128 * j;          // 512 uint4
        int n = idx >> 3, q = idx & 7;
        uint4 u = ((const uint4*)Wg)[idx];
        __half* p = &Wt[n * SA + q * 8];
        *(unsigned*)(p + 0) = u.x;
        *(unsigned*)(p + 2) = u.y;
        *(unsigned*)(p + 4) = u.z;
        *(unsigned*)(p + 6) = u.w;
    }
}

// ---------------- GEMM1: xs = (x @ W1) * dis -> fp16 bufA (HMMA) ------------
__global__ void k_gemm1(const float* __restrict__ x) {
    __shared__ __half As[64 * SA];
    __shared__ __half Wt[64 * SA];
    int t = threadIdx.x;
    int base = blockIdx.x * 64;
    load_Wt_smem(Wt, g_W1t);
    // load 64 rows of x fp32 -> fp16 (8 float4 per thread)
    #pragma unroll
    for (int j = 0; j < 8; j++) {
        int idx = t + 128 * j;          // 1024 float4
        int r = idx >> 4, q = idx & 15;
        int row = base + r;
        float4 f = (row < N_NODES) ? ((const float4*)x)[(long long)row * 16 + q]
                                   : make_float4(0.f, 0.f, 0.f, 0.f);
        __half* p = &As[r * SA + q * 4];
        *(__half2*)(p + 0) = __floats2half2_rn(f.x, f.y);
        *(__half2*)(p + 2) = __floats2half2_rn(f.z, f.w);
    }
    __syncthreads();
    mma_body(As, Wt, base);
}

// ---------------- GEMM2: xs2 = (h @ W2) * dis -> fp16 bufA (HMMA) -----------
__global__ void k_gemm2() {
    __shared__ __half As[64 * SA];
    __shared__ __half Wt[64 * SA];
    int t = threadIdx.x;
    int base = blockIdx.x * 64;
    load_Wt_smem(Wt, g_W2t);
    // load 64 rows of bufH fp16 (4 uint4 per thread)
    #pragma unroll
    for (int j = 0; j < 4; j++) {
        int idx = t + 128 * j;          // 512 uint4
        int r = idx >> 3, q = idx & 7;
        int row = base + r;
        uint4 u = (row < N_NODES) ? ((const uint4*)g_bufH)[(long long)row * 8 + q]
                                  : make_uint4(0u, 0u, 0u, 0u);
        __half* p = &As[r * SA + q * 8];
        *(unsigned*)(p + 0) = u.x;
        *(unsigned*)(p + 2) = u.y;
        *(unsigned*)(p + 4) = u.z;
        *(unsigned*)(p + 6) = u.w;
    }
    __syncthreads();
    mma_body(As, Wt, base);
}

// ---------------- agg0 fused: h = relu(dis*(sum+xs)+b1) -> fp16 bufH ----------
__global__ void k_agg0(const float* __restrict__ b1) {
    int t = blockIdx.x * blockDim.x + threadIdx.x;
    int node = t >> 3;
    int lane = t & 7;
    if (node >= N_NODES) return;
    int beg = g_rowptr[node];
    int cnt = g_cnt[node];
    const uint4* A = (const uint4*)g_bufA;
    float acc[8] = {};
    int i = 0;
    for (; i + 4 <= cnt; i += 4) {
        int s0 = __ldg(&g_srcs[beg + i + 0]);
        int s1 = __ldg(&g_srcs[beg + i + 1]);
        int s2 = __ldg(&g_srcs[beg + i + 2]);
        int s3 = __ldg(&g_srcs[beg + i + 3]);
        uint4 u0 = __ldg(&A[s0 * 8 + lane]);
        uint4 u1 = __ldg(&A[s1 * 8 + lane]);
        uint4 u2 = __ldg(&A[s2 * 8 + lane]);
        uint4 u3 = __ldg(&A[s3 * 8 + lane]);
        acc_half8(acc, u0); acc_half8(acc, u1);
        acc_half8(acc, u2); acc_half8(acc, u3);
    }
    for (; i < cnt; i++) {
        int s = __ldg(&g_srcs[beg + i]);
        acc_half8(acc, __ldg(&A[s * 8 + lane]));
    }
    float dis = g_dis[node];
    float xs[8] = {};
    acc_half8(xs, __ldg(&A[node * 8 + lane]));
    uint4 out;
    float h0, h1;
    h0 = fmaxf(dis * (acc[0] + xs[0]) + b1[lane * 8 + 0], 0.0f);
    h1 = fmaxf(dis * (acc[1] + xs[1]) + b1[lane * 8 + 1], 0.0f);
    *(__half2*)&out.x = __floats2half2_rn(h0, h1);
    h0 = fmaxf(dis * (acc[2] + xs[2]) + b1[lane * 8 + 2], 0.0f);
    h1 = fmaxf(dis * (acc[3] + xs[3]) + b1[lane * 8 + 3], 0.0f);
    *(__half2*)&out.y = __floats2half2_rn(h0, h1);
    h0 = fmaxf(dis * (acc[4] + xs[4]) + b1[lane * 8 + 4], 0.0f);
    h1 = fmaxf(dis * (acc[5] + xs[5]) + b1[lane * 8 + 5], 0.0f);
    *(__half2*)&out.z = __floats2half2_rn(h0, h1);
    h0 = fmaxf(dis * (acc[6] + xs[6]) + b1[lane * 8 + 6], 0.0f);
    h1 = fmaxf(dis * (acc[7] + xs[7]) + b1[lane * 8 + 7], 0.0f);
    *(__half2*)&out.w = __floats2half2_rn(h0, h1);
    ((uint4*)g_bufH)[node * 8 + lane] = out;
}

// ---------------- agg1 fused with relu + mean-pool ----------------
__global__ void k_agg1(const float* __restrict__ b2, const int* __restrict__ batch) {
    __shared__ float hacc[32 * F];
    int tid = threadIdx.x;
    int s = tid >> 3;
    int lane = tid & 7;
    int base = blockIdx.x * 32;
    int node = base + s;
    int beg = g_rowptr[node];
    int cnt = g_cnt[node];
    const uint4* A = (const uint4*)g_bufA;
    float acc[8] = {};
    int i = 0;
    for (; i + 4 <= cnt; i += 4) {
        int s0 = __ldg(&g_srcs[beg + i + 0]);
        int s1 = __ldg(&g_srcs[beg + i + 1]);
        int s2 = __ldg(&g_srcs[beg + i + 2]);
        int s3 = __ldg(&g_srcs[beg + i + 3]);
        uint4 u0 = __ldg(&A[s0 * 8 + lane]);
        uint4 u1 = __ldg(&A[s1 * 8 + lane]);
        uint4 u2 = __ldg(&A[s2 * 8 + lane]);
        uint4 u3 = __ldg(&A[s3 * 8 + lane]);
        acc_half8(acc, u0); acc_half8(acc, u1);
        acc_half8(acc, u2); acc_half8(acc, u3);
    }
    for (; i < cnt; i++) {
        int sidx = __ldg(&g_srcs[beg + i]);
        acc_half8(acc, __ldg(&A[sidx * 8 + lane]));
    }
    float dis = g_dis[node];
    float xs[8] = {};
    acc_half8(xs, __ldg(&A[node * 8 + lane]));
    float h[8];
    #pragma unroll
    for (int j = 0; j < 8; j++)
        h[j] = fmaxf(dis * (acc[j] + xs[j]) + b2[lane * 8 + j], 0.0f);
    #pragma unroll
    for (int j = 0; j < 8; j++) hacc[s * F + lane * 8 + j] = h[j];
    __syncthreads();

    int g0 = batch[base];
    int g1 = batch[base + 31];
    if (g0 == g1) {
        #pragma unroll
        for (int off = 16; off >= 1; off >>= 1) {
            if (s < off) {
                #pragma unroll
                for (int j = 0; j < 8; j++)
                    hacc[s * F + lane * 8 + j] += hacc[(s + off) * F + lane * 8 + j];
            }
            __syncthreads();
        }
        if (tid < 16) {
            float4 v = ((float4*)hacc)[tid];
            red_v4(&g_gsum[g0 * F + tid * 4], v.x, v.y, v.z, v.w);
        }
    } else {
        int g = batch[node];
        red_v4(&g_gsum[g * F + lane * 8 + 0], h[0], h[1], h[2], h[3]);
        red_v4(&g_gsum[g * F + lane * 8 + 4], h[4], h[5], h[6], h[7]);
    }
}

// ---------------- head ----------------
__global__ void k_head(const float* __restrict__ topo, const float* __restrict__ Wlin,
                       const float* __restrict__ blin, float* __restrict__ out) {
    int t = threadIdx.x;
    int g = t >> 2, c = t & 3;
    float inv = 1.0f / fmaxf(g_gcnt[g], 1.0f);
    float acc = blin[c];
    #pragma unroll
    for (int k = 0; k < F; k++)
        acc = fmaf(g_gsum[g * F + k] * inv, Wlin[k * NUM_CLASSES + c], acc);
    #pragma unroll
    for (int k = 0; k < TOPO_DIM; k++)
        acc = fmaf(topo[g * TOPO_DIM + k], Wlin[(F + k) * NUM_CLASSES + c], acc);
    out[g * NUM_CLASSES + c] = acc;
}

extern "C" void kernel_launch(void* const* d_in, const int* in_sizes, int n_in,
                              void* d_out, int out_size) {
    const float* x    = (const float*)d_in[0];
    const int*   edge = (const int*)d_in[1];
    const int*   batch= (const int*)d_in[2];
    const float* topo = (const float*)d_in[3];
    const float* W1   = (const float*)d_in[4];
    const float* b1   = (const float*)d_in[5];
    const float* W2   = (const float*)d_in[6];
    const float* b2   = (const float*)d_in[7];
    const float* Wlin = (const float*)d_in[8];
    const float* blin = (const float*)d_in[9];
    float* out = (float*)d_out;

    const int gblocks = (N_NODES + 63) / 64;          // 1563
    const int ablocks = N_NODES * 8 / 256;            // 3125 exact
    const int eblocks = (N_EDGES / 4 + 255) / 256;    // 1563

    k_init<<<(N_NODES + 255) / 256, 256>>>();
    k_prepW<<<1, 256>>>(W1, W2);
    k_degree<<<eblocks, 256>>>(edge);
    k_scan<<<SCAN_NBLK, SCAN_BLK>>>(batch);
    k_bin<<<eblocks, 256>>>(edge);
    k_gemm1<<<gblocks, 128>>>(x);
    k_agg0<<<ablocks, 256>>>(b1);
    k_gemm2<<<gblocks, 128>>>();
    k_agg1<<<ablocks, 256>>>(b2, batch);
    k_head<<<1, 256>>>(topo, Wlin, blin, out);
}

// round 10
// speedup vs baseline: 1.1548x; 1.0610x over previous
#include <cuda_runtime.h>
#include <cuda_fp16.h>

#define N_NODES 100000
#define N_EDGES 1600000
#define F 64
#define NUM_GRAPHS 64
#define TOPO_DIM 16
#define NUM_CLASSES 4

#define SCAN_BLK 512
#define SCAN_NBLK ((N_NODES + SCAN_BLK - 1) / SCAN_BLK)   // 196

#define SA 72   // smem row stride (halfs) — conflict-free for frag loads

// Scratch (device globals; allocation-free per harness rules)
__device__ int      g_cnt[N_NODES];
__device__ int      g_rowptr[N_NODES];
__device__ int      g_fill[N_NODES];
__device__ int      g_srcs[N_EDGES];
__device__ int      g_lscan[N_NODES];
__device__ int      g_bsum[SCAN_NBLK];
__device__ int      g_boff[SCAN_NBLK];
__device__ float    g_dis[N_NODES];
__device__ __half   g_bufA[N_NODES * F];   // xs (fp16) — gathered buffer
__device__ __half   g_bufH[N_NODES * F];   // h after layer1 relu (fp16)
__device__ __half   g_W1t[F * F];          // W1 transposed fp16 [n][k]
__device__ __half   g_W2t[F * F];          // W2 transposed fp16 [n][k]
__device__ float    g_gsum[NUM_GRAPHS * F];
__device__ float    g_gcnt[NUM_GRAPHS];

// ---------------- init ----------------
__global__ void k_init() {
    int i = blockIdx.x * blockDim.x + threadIdx.x;
    if (i < N_NODES) g_cnt[i] = 0;
    if (i < NUM_GRAPHS * F) g_gsum[i] = 0.0f;
    if (i < NUM_GRAPHS) g_gcnt[i] = 0.0f;
}

// ---------------- weight prep: transpose + fp16 ----------------
__global__ void k_prepW(const float* __restrict__ W1, const float* __restrict__ W2) {
    int t = threadIdx.x;   // 256
    #pragma unroll
    for (int j = 0; j < 16; j++) {
        int e = t + 256 * j;        // 4096
        int k = e >> 6, n = e & 63;
        g_W1t[n * F + k] = __float2half(W1[e]);
        g_W2t[n * F + k] = __float2half(W2[e]);
    }
}

// ---------------- degree histogram (4 edges/thread, MLP=4) ----------------
__global__ void k_degree(const int* __restrict__ edge) {
    int t = blockIdx.x * blockDim.x + threadIdx.x;
    if (t < N_EDGES / 4) {
        int4 d = ((const int4*)(edge + N_EDGES))[t];
        atomicAdd(&g_cnt[d.x], 1);
        atomicAdd(&g_cnt[d.y], 1);
        atomicAdd(&g_cnt[d.z], 1);
        atomicAdd(&g_cnt[d.w], 1);
    }
}

// ---------------- 3-kernel prefix scan (proven fast) + dis + gcnt ------------
__global__ void k_scan1(const int* __restrict__ batch) {
    __shared__ int s[SCAN_BLK];
    int t = threadIdx.x;
    int i = blockIdx.x * SCAN_BLK + t;
    int v = (i < N_NODES) ? g_cnt[i] : 0;
    if (i < N_NODES) {
        g_dis[i] = rsqrtf((float)v + 1.0f);
        atomicAdd(&g_gcnt[batch[i]], 1.0f);
    }
    s[t] = v;
    __syncthreads();
    #pragma unroll
    for (int off = 1; off < SCAN_BLK; off <<= 1) {
        int add = (t >= off) ? s[t - off] : 0;
        __syncthreads();
        s[t] += add;
        __syncthreads();
    }
    if (i < N_NODES) g_lscan[i] = s[t] - v;
    if (t == SCAN_BLK - 1) g_bsum[blockIdx.x] = s[t];
}

__global__ void k_scan2() {
    __shared__ int s[256];
    int t = threadIdx.x;
    int v = (t < SCAN_NBLK) ? g_bsum[t] : 0;
    s[t] = v;
    __syncthreads();
    #pragma unroll
    for (int off = 1; off < 256; off <<= 1) {
        int add = (t >= off) ? s[t - off] : 0;
        __syncthreads();
        s[t] += add;
        __syncthreads();
    }
    if (t < SCAN_NBLK) g_boff[t] = s[t] - v;
}

__global__ void k_scan3() {
    int i = blockIdx.x * blockDim.x + threadIdx.x;
    if (i < N_NODES) {
        int rp = g_lscan[i] + g_boff[i / SCAN_BLK];
        g_rowptr[i] = rp;
        g_fill[i] = rp;
    }
}

// ---------------- bin edges by dst (4 edges/thread, MLP=4) ----------------
__global__ void k_bin(const int* __restrict__ edge) {
    int t = blockIdx.x * blockDim.x + threadIdx.x;
    if (t < N_EDGES / 4) {
        int4 s = ((const int4*)edge)[t];
        int4 d = ((const int4*)(edge + N_EDGES))[t];
        int p0 = atomicAdd(&g_fill[d.x], 1);
        int p1 = atomicAdd(&g_fill[d.y], 1);
        int p2 = atomicAdd(&g_fill[d.z], 1);
        int p3 = atomicAdd(&g_fill[d.w], 1);
        g_srcs[p0] = s.x;
        g_srcs[p1] = s.y;
        g_srcs[p2] = s.z;
        g_srcs[p3] = s.w;
    }
}

// ---------------- helpers ----------------
__device__ __forceinline__ void acc_half8(float* acc, uint4 u) {
    float2 f;
    f = __half22float2(*(__half2*)&u.x); acc[0] += f.x; acc[1] += f.y;
    f = __half22float2(*(__half2*)&u.y); acc[2] += f.x; acc[3] += f.y;
    f = __half22float2(*(__half2*)&u.z); acc[4] += f.x; acc[5] += f.y;
    f = __half22float2(*(__half2*)&u.w); acc[6] += f.x; acc[7] += f.y;
}

__device__ __forceinline__ void red_v4(float* p, float a, float b, float c, float d) {
    unsigned long long ga;
    asm("cvta.to.global.u64 %0, %1;" : "=l"(ga) : "l"(p));
    asm volatile("red.global.add.v4.f32 [%0], {%1,%2,%3,%4};"
                 :: "l"(ga), "f"(a), "f"(b), "f"(c), "f"(d) : "memory");
}

__device__ __forceinline__ void mma16816(float* c,
    unsigned a0, unsigned a1, unsigned a2, unsigned a3,
    unsigned b0, unsigned b1) {
    asm volatile("mma.sync.aligned.m16n8k16.row.col.f32.f16.f16.f32 "
        "{%0,%1,%2,%3}, {%4,%5,%6,%7}, {%8,%9}, {%0,%1,%2,%3};"
        : "+f"(c[0]), "+f"(c[1]), "+f"(c[2]), "+f"(c[3])
        : "r"(a0), "r"(a1), "r"(a2), "r"(a3), "r"(b0), "r"(b1));
}

// Shared mma mainloop + epilogue: As[64][SA] fp16 staged, Wt smem staged.
// Block = 128 threads (4 warps), warp w handles rows w*16..w*16+15, all 64 cols.
__device__ __forceinline__ void mma_body(const __half* As, const __half* Wt, int base) {
    int lane = threadIdx.x & 31;
    int w = threadIdx.x >> 5;
    int g = lane >> 2, tg = lane & 3;
    int R = w * 16;
    float c[8][4] = {};
    #pragma unroll
    for (int k0 = 0; k0 < F; k0 += 16) {
        unsigned a0 = *(const unsigned*)&As[(R + g) * SA + k0 + tg * 2];
        unsigned a1 = *(const unsigned*)&As[(R + g + 8) * SA + k0 + tg * 2];
        unsigned a2 = *(const unsigned*)&As[(R + g) * SA + k0 + tg * 2 + 8];
        unsigned a3 = *(const unsigned*)&As[(R + g + 8) * SA + k0 + tg * 2 + 8];
        #pragma unroll
        for (int n = 0; n < 8; n++) {
            unsigned b0 = *(const unsigned*)&Wt[(n * 8 + g) * SA + k0 + tg * 2];
            unsigned b1 = *(const unsigned*)&Wt[(n * 8 + g) * SA + k0 + tg * 2 + 8];
            mma16816(c[n], a0, a1, a2, a3, b0, b1);
        }
    }
    // epilogue: scale by dis, fp16, store to bufA
    int row0 = base + R + g;
    int row1 = row0 + 8;
    float dis0 = (row0 < N_NODES) ? g_dis[row0] : 0.0f;
    float dis1 = (row1 < N_NODES) ? g_dis[row1] : 0.0f;
    #pragma unroll
    for (int n = 0; n < 8; n++) {
        int col = n * 8 + tg * 2;
        if (row0 < N_NODES) {
            __half2 h = __floats2half2_rn(c[n][0] * dis0, c[n][1] * dis0);
            *(__half2*)&g_bufA[row0 * F + col] = h;
        }
        if (row1 < N_NODES) {
            __half2 h = __floats2half2_rn(c[n][2] * dis1, c[n][3] * dis1);
            *(__half2*)&g_bufA[row1 * F + col] = h;
        }
    }
}

__device__ __forceinline__ void load_Wt_smem(__half* Wt, const __half* Wg) {
    int t = threadIdx.x;   // 128
    #pragma unroll
    for (int j = 0; j < 4; j++) {
        int idx = t + 128 * j;          // 512 uint4
        int n = idx >> 3, q = idx & 7;
        uint4 u = ((const uint4*)Wg)[idx];
        __half* p = &Wt[n * SA + q * 8];
        *(unsigned*)(p + 0) = u.x;
        *(unsigned*)(p + 2) = u.y;
        *(unsigned*)(p + 4) = u.z;
        *(unsigned*)(p + 6) = u.w;
    }
}

// ---------------- GEMM1: xs = (x @ W1) * dis -> fp16 bufA (HMMA) ------------
__global__ void k_gemm1(const float* __restrict__ x) {
    __shared__ __half As[64 * SA];
    __shared__ __half Wt[64 * SA];
    int t = threadIdx.x;
    int base = blockIdx.x * 64;
    load_Wt_smem(Wt, g_W1t);
    #pragma unroll
    for (int j = 0; j < 8; j++) {
        int idx = t + 128 * j;          // 1024 float4
        int r = idx >> 4, q = idx & 15;
        int row = base + r;
        float4 f = (row < N_NODES) ? ((const float4*)x)[(long long)row * 16 + q]
                                   : make_float4(0.f, 0.f, 0.f, 0.f);
        __half* p = &As[r * SA + q * 4];
        *(__half2*)(p + 0) = __floats2half2_rn(f.x, f.y);
        *(__half2*)(p + 2) = __floats2half2_rn(f.z, f.w);
    }
    __syncthreads();
    mma_body(As, Wt, base);
}

// ---------------- GEMM2: xs2 = (h @ W2) * dis -> fp16 bufA (HMMA) -----------
__global__ void k_gemm2() {
    __shared__ __half As[64 * SA];
    __shared__ __half Wt[64 * SA];
    int t = threadIdx.x;
    int base = blockIdx.x * 64;
    load_Wt_smem(Wt, g_W2t);
    #pragma unroll
    for (int j = 0; j < 4; j++) {
        int idx = t + 128 * j;          // 512 uint4
        int r = idx >> 3, q = idx & 7;
        int row = base + r;
        uint4 u = (row < N_NODES) ? ((const uint4*)g_bufH)[(long long)row * 8 + q]
                                  : make_uint4(0u, 0u, 0u, 0u);
        __half* p = &As[r * SA + q * 8];
        *(unsigned*)(p + 0) = u.x;
        *(unsigned*)(p + 2) = u.y;
        *(unsigned*)(p + 4) = u.z;
        *(unsigned*)(p + 6) = u.w;
    }
    __syncthreads();
    mma_body(As, Wt, base);
}

// ---------------- agg0 fused: h = relu(dis*(sum+xs)+b1) -> fp16 bufH ----------
__global__ void k_agg0(const float* __restrict__ b1) {
    int t = blockIdx.x * blockDim.x + threadIdx.x;
    int node = t >> 3;
    int lane = t & 7;
    if (node >= N_NODES) return;
    int beg = g_rowptr[node];
    int cnt = g_cnt[node];
    const uint4* A = (const uint4*)g_bufA;
    float acc[8] = {};
    int i = 0;
    for (; i + 4 <= cnt; i += 4) {
        int s0 = __ldg(&g_srcs[beg + i + 0]);
        int s1 = __ldg(&g_srcs[beg + i + 1]);
        int s2 = __ldg(&g_srcs[beg + i + 2]);
        int s3 = __ldg(&g_srcs[beg + i + 3]);
        uint4 u0 = __ldg(&A[s0 * 8 + lane]);
        uint4 u1 = __ldg(&A[s1 * 8 + lane]);
        uint4 u2 = __ldg(&A[s2 * 8 + lane]);
        uint4 u3 = __ldg(&A[s3 * 8 + lane]);
        acc_half8(acc, u0); acc_half8(acc, u1);
        acc_half8(acc, u2); acc_half8(acc, u3);
    }
    for (; i < cnt; i++) {
        int s = __ldg(&g_srcs[beg + i]);
        acc_half8(acc, __ldg(&A[s * 8 + lane]));
    }
    float dis = g_dis[node];
    float xs[8] = {};
    acc_half8(xs, __ldg(&A[node * 8 + lane]));
    uint4 out;
    float h0, h1;
    h0 = fmaxf(dis * (acc[0] + xs[0]) + b1[lane * 8 + 0], 0.0f);
    h1 = fmaxf(dis * (acc[1] + xs[1]) + b1[lane * 8 + 1], 0.0f);
    *(__half2*)&out.x = __floats2half2_rn(h0, h1);
    h0 = fmaxf(dis * (acc[2] + xs[2]) + b1[lane * 8 + 2], 0.0f);
    h1 = fmaxf(dis * (acc[3] + xs[3]) + b1[lane * 8 + 3], 0.0f);
    *(__half2*)&out.y = __floats2half2_rn(h0, h1);
    h0 = fmaxf(dis * (acc[4] + xs[4]) + b1[lane * 8 + 4], 0.0f);
    h1 = fmaxf(dis * (acc[5] + xs[5]) + b1[lane * 8 + 5], 0.0f);
    *(__half2*)&out.z = __floats2half2_rn(h0, h1);
    h0 = fmaxf(dis * (acc[6] + xs[6]) + b1[lane * 8 + 6], 0.0f);
    h1 = fmaxf(dis * (acc[7] + xs[7]) + b1[lane * 8 + 7], 0.0f);
    *(__half2*)&out.w = __floats2half2_rn(h0, h1);
    ((uint4*)g_bufH)[node * 8 + lane] = out;
}

// ---------------- agg1 fused with relu + mean-pool ----------------
__global__ void k_agg1(const float* __restrict__ b2, const int* __restrict__ batch) {
    __shared__ float hacc[32 * F];
    int tid = threadIdx.x;
    int s = tid >> 3;
    int lane = tid & 7;
    int base = blockIdx.x * 32;
    int node = base + s;
    int beg = g_rowptr[node];
    int cnt = g_cnt[node];
    const uint4* A = (const uint4*)g_bufA;
    float acc[8] = {};
    int i = 0;
    for (; i + 4 <= cnt; i += 4) {
        int s0 = __ldg(&g_srcs[beg + i + 0]);
        int s1 = __ldg(&g_srcs[beg + i + 1]);
        int s2 = __ldg(&g_srcs[beg + i + 2]);
        int s3 = __ldg(&g_srcs[beg + i + 3]);
        uint4 u0 = __ldg(&A[s0 * 8 + lane]);
        uint4 u1 = __ldg(&A[s1 * 8 + lane]);
        uint4 u2 = __ldg(&A[s2 * 8 + lane]);
        uint4 u3 = __ldg(&A[s3 * 8 + lane]);
        acc_half8(acc, u0); acc_half8(acc, u1);
        acc_half8(acc, u2); acc_half8(acc, u3);
    }
    for (; i < cnt; i++) {
        int sidx = __ldg(&g_srcs[beg + i]);
        acc_half8(acc, __ldg(&A[sidx * 8 + lane]));
    }
    float dis = g_dis[node];
    float xs[8] = {};
    acc_half8(xs, __ldg(&A[node * 8 + lane]));
    float h[8];
    #pragma unroll
    for (int j = 0; j < 8; j++)
        h[j] = fmaxf(dis * (acc[j] + xs[j]) + b2[lane * 8 + j], 0.0f);
    #pragma unroll
    for (int j = 0; j < 8; j++) hacc[s * F + lane * 8 + j] = h[j];
    __syncthreads();

    int g0 = batch[base];
    int g1 = batch[base + 31];
    if (g0 == g1) {
        #pragma unroll
        for (int off = 16; off >= 1; off >>= 1) {
            if (s < off) {
                #pragma unroll
                for (int j = 0; j < 8; j++)
                    hacc[s * F + lane * 8 + j] += hacc[(s + off) * F + lane * 8 + j];
            }
            __syncthreads();
        }
        if (tid < 16) {
            float4 v = ((float4*)hacc)[tid];
            red_v4(&g_gsum[g0 * F + tid * 4], v.x, v.y, v.z, v.w);
        }
    } else {
        int g = batch[node];
        red_v4(&g_gsum[g * F + lane * 8 + 0], h[0], h[1], h[2], h[3]);
        red_v4(&g_gsum[g * F + lane * 8 + 4], h[4], h[5], h[6], h[7]);
    }
}

// ---------------- head ----------------
__global__ void k_head(const float* __restrict__ topo, const float* __restrict__ Wlin,
                       const float* __restrict__ blin, float* __restrict__ out) {
    int t = threadIdx.x;
    int g = t >> 2, c = t & 3;
    float inv = 1.0f / fmaxf(g_gcnt[g], 1.0f);
    float acc = blin[c];
    #pragma unroll
    for (int k = 0; k < F; k++)
        acc = fmaf(g_gsum[g * F + k] * inv, Wlin[k * NUM_CLASSES + c], acc);
    #pragma unroll
    for (int k = 0; k < TOPO_DIM; k++)
        acc = fmaf(topo[g * TOPO_DIM + k], Wlin[(F + k) * NUM_CLASSES + c], acc);
    out[g * NUM_CLASSES + c] = acc;
}

extern "C" void kernel_launch(void* const* d_in, const int* in_sizes, int n_in,
                              void* d_out, int out_size) {
    const float* x    = (const float*)d_in[0];
    const int*   edge = (const int*)d_in[1];
    const int*   batch= (const int*)d_in[2];
    const float* topo = (const float*)d_in[3];
    const float* W1   = (const float*)d_in[4];
    const float* b1   = (const float*)d_in[5];
    const float* W2   = (const float*)d_in[6];
    const float* b2   = (const float*)d_in[7];
    const float* Wlin = (const float*)d_in[8];
    const float* blin = (const float*)d_in[9];
    float* out = (float*)d_out;

    const int gblocks = (N_NODES + 63) / 64;          // 1563
    const int ablocks = N_NODES * 8 / 256;            // 3125 exact
    const int eblocks = (N_EDGES / 4 + 255) / 256;    // 1563

    k_init<<<(N_NODES + 255) / 256, 256>>>();
    k_prepW<<<1, 256>>>(W1, W2);
    k_degree<<<eblocks, 256>>>(edge);
    k_scan1<<<SCAN_NBLK, SCAN_BLK>>>(batch);
    k_scan2<<<1, 256>>>();
    k_scan3<<<(N_NODES + 255) / 256, 256>>>();
    k_bin<<<eblocks, 256>>>(edge);
    k_gemm1<<<gblocks, 128>>>(x);
    k_agg0<<<ablocks, 256>>>(b1);
    k_gemm2<<<gblocks, 128>>>();
    k_agg1<<<ablocks, 256>>>(b2, batch);
    k_head<<<1, 256>>>(topo, Wlin, blin, out);
}

// round 11
// speedup vs baseline: 1.7139x; 1.4841x over previous
#include <cuda_runtime.h>
#include <cuda_fp16.h>

#define N_NODES 100000
#define N_EDGES 1600000
#define F 64
#define NUM_GRAPHS 64
#define TOPO_DIM 16
#define NUM_CLASSES 4

#define SCAN_BLK 512
#define SCAN_NBLK ((N_NODES + SCAN_BLK - 1) / SCAN_BLK)   // 196

#define SA 72   // smem row stride (halfs) — conflict-free for frag loads

// Scratch (device globals; allocation-free per harness rules)
__device__ int      g_cnt[N_NODES];
__device__ int      g_rowptr[N_NODES];
__device__ int      g_fill[N_NODES];
__device__ int      g_srcs[N_EDGES];
__device__ int      g_lscan[N_NODES];
__device__ int      g_bsum[SCAN_NBLK];
__device__ int      g_boff[SCAN_NBLK];
__device__ float    g_dis[N_NODES];
__device__ __half   g_bufA[N_NODES * F];   // xs (fp16) — gathered buffer
__device__ __half   g_bufH[N_NODES * F];   // h after layer1 relu (fp16)
__device__ __half   g_W1t[F * F];          // W1 transposed fp16 [n][k]
__device__ __half   g_W2t[F * F];          // W2 transposed fp16 [n][k]
__device__ float    g_gsum[NUM_GRAPHS * F];
__device__ float    g_gcnt[NUM_GRAPHS];

// ---------------- init ----------------
__global__ void k_init() {
    int i = blockIdx.x * blockDim.x + threadIdx.x;
    if (i < N_NODES) g_cnt[i] = 0;
    if (i < NUM_GRAPHS * F) g_gsum[i] = 0.0f;
    if (i < NUM_GRAPHS) g_gcnt[i] = 0.0f;
}

// ---------------- weight prep: transpose + fp16 ----------------
__global__ void k_prepW(const float* __restrict__ W1, const float* __restrict__ W2) {
    int t = threadIdx.x;   // 256
    #pragma unroll
    for (int j = 0; j < 16; j++) {
        int e = t + 256 * j;        // 4096
        int k = e >> 6, n = e & 63;
        g_W1t[n * F + k] = __float2half(W1[e]);
        g_W2t[n * F + k] = __float2half(W2[e]);
    }
}

// ---------------- degree histogram (4 edges/thread, MLP=4) ----------------
__global__ void k_degree(const int* __restrict__ edge) {
    int t = blockIdx.x * blockDim.x + threadIdx.x;
    if (t < N_EDGES / 4) {
        int4 d = ((const int4*)(edge + N_EDGES))[t];
        atomicAdd(&g_cnt[d.x], 1);
        atomicAdd(&g_cnt[d.y], 1);
        atomicAdd(&g_cnt[d.z], 1);
        atomicAdd(&g_cnt[d.w], 1);
    }
}

// ---------------- 3-kernel prefix scan + dis + warp-aggregated gcnt ----------
__global__ void k_scan1(const int* __restrict__ batch) {
    __shared__ int s[SCAN_BLK];
    int t = threadIdx.x;
    int i = blockIdx.x * SCAN_BLK + t;
    int v = (i < N_NODES) ? g_cnt[i] : 0;
    if (i < N_NODES) {
        g_dis[i] = rsqrtf((float)v + 1.0f);
        // warp-aggregated graph count: batch is sorted, so lanes mostly share
        // one graph id -> one atomic per (warp, distinct id) instead of 32.
        int g = batch[i];
        unsigned active = __activemask();
        unsigned mask = __match_any_sync(active, g);
        int leader = __ffs(mask) - 1;
        if ((t & 31) == leader)
            atomicAdd(&g_gcnt[g], (float)__popc(mask));
    }
    s[t] = v;
    __syncthreads();
    #pragma unroll
    for (int off = 1; off < SCAN_BLK; off <<= 1) {
        int add = (t >= off) ? s[t - off] : 0;
        __syncthreads();
        s[t] += add;
        __syncthreads();
    }
    if (i < N_NODES) g_lscan[i] = s[t] - v;
    if (t == SCAN_BLK - 1) g_bsum[blockIdx.x] = s[t];
}

__global__ void k_scan2() {
    __shared__ int s[256];
    int t = threadIdx.x;
    int v = (t < SCAN_NBLK) ? g_bsum[t] : 0;
    s[t] = v;
    __syncthreads();
    #pragma unroll
    for (int off = 1; off < 256; off <<= 1) {
        int add = (t >= off) ? s[t - off] : 0;
        __syncthreads();
        s[t] += add;
        __syncthreads();
    }
    if (t < SCAN_NBLK) g_boff[t] = s[t] - v;
}

__global__ void k_scan3() {
    int i = blockIdx.x * blockDim.x + threadIdx.x;
    if (i < N_NODES) {
        int rp = g_lscan[i] + g_boff[i / SCAN_BLK];
        g_rowptr[i] = rp;
        g_fill[i] = rp;
    }
}

// ---------------- bin edges by dst (4 edges/thread, MLP=4) ----------------
__global__ void k_bin(const int* __restrict__ edge) {
    int t = blockIdx.x * blockDim.x + threadIdx.x;
    if (t < N_EDGES / 4) {
        int4 s = ((const int4*)edge)[t];
        int4 d = ((const int4*)(edge + N_EDGES))[t];
        int p0 = atomicAdd(&g_fill[d.x], 1);
        int p1 = atomicAdd(&g_fill[d.y], 1);
        int p2 = atomicAdd(&g_fill[d.z], 1);
        int p3 = atomicAdd(&g_fill[d.w], 1);
        g_srcs[p0] = s.x;
        g_srcs[p1] = s.y;
        g_srcs[p2] = s.z;
        g_srcs[p3] = s.w;
    }
}

// ---------------- helpers ----------------
__device__ __forceinline__ void acc_half8(float* acc, uint4 u) {
    float2 f;
    f = __half22float2(*(__half2*)&u.x); acc[0] += f.x; acc[1] += f.y;
    f = __half22float2(*(__half2*)&u.y); acc[2] += f.x; acc[3] += f.y;
    f = __half22float2(*(__half2*)&u.z); acc[4] += f.x; acc[5] += f.y;
    f = __half22float2(*(__half2*)&u.w); acc[6] += f.x; acc[7] += f.y;
}

__device__ __forceinline__ void red_v4(float* p, float a, float b, float c, float d) {
    unsigned long long ga;
    asm("cvta.to.global.u64 %0, %1;" : "=l"(ga) : "l"(p));
    asm volatile("red.global.add.v4.f32 [%0], {%1,%2,%3,%4};"
                 :: "l"(ga), "f"(a), "f"(b), "f"(c), "f"(d) : "memory");
}

__device__ __forceinline__ void mma16816(float* c,
    unsigned a0, unsigned a1, unsigned a2, unsigned a3,
    unsigned b0, unsigned b1) {
    asm volatile("mma.sync.aligned.m16n8k16.row.col.f32.f16.f16.f32 "
        "{%0,%1,%2,%3}, {%4,%5,%6,%7}, {%8,%9}, {%0,%1,%2,%3};"
        : "+f"(c[0]), "+f"(c[1]), "+f"(c[2]), "+f"(c[3])
        : "r"(a0), "r"(a1), "r"(a2), "r"(a3), "r"(b0), "r"(b1));
}

// Shared mma mainloop + epilogue: As[64][SA] fp16 staged, Wt smem staged.
// Block = 128 threads (4 warps), warp w handles rows w*16..w*16+15, all 64 cols.
__device__ __forceinline__ void mma_body(const __half* As, const __half* Wt, int base) {
    int lane = threadIdx.x & 31;
    int w = threadIdx.x >> 5;
    int g = lane >> 2, tg = lane & 3;
    int R = w * 16;
    float c[8][4] = {};
    #pragma unroll
    for (int k0 = 0; k0 < F; k0 += 16) {
        unsigned a0 = *(const unsigned*)&As[(R + g) * SA + k0 + tg * 2];
        unsigned a1 = *(const unsigned*)&As[(R + g + 8) * SA + k0 + tg * 2];
        unsigned a2 = *(const unsigned*)&As[(R + g) * SA + k0 + tg * 2 + 8];
        unsigned a3 = *(const unsigned*)&As[(R + g + 8) * SA + k0 + tg * 2 + 8];
        #pragma unroll
        for (int n = 0; n < 8; n++) {
            unsigned b0 = *(const unsigned*)&Wt[(n * 8 + g) * SA + k0 + tg * 2];
            unsigned b1 = *(const unsigned*)&Wt[(n * 8 + g) * SA + k0 + tg * 2 + 8];
            mma16816(c[n], a0, a1, a2, a3, b0, b1);
        }
    }
    int row0 = base + R + g;
    int row1 = row0 + 8;
    float dis0 = (row0 < N_NODES) ? g_dis[row0] : 0.0f;
    float dis1 = (row1 < N_NODES) ? g_dis[row1] : 0.0f;
    #pragma unroll
    for (int n = 0; n < 8; n++) {
        int col = n * 8 + tg * 2;
        if (row0 < N_NODES) {
            __half2 h = __floats2half2_rn(c[n][0] * dis0, c[n][1] * dis0);
            *(__half2*)&g_bufA[row0 * F + col] = h;
        }
        if (row1 < N_NODES) {
            __half2 h = __floats2half2_rn(c[n][2] * dis1, c[n][3] * dis1);
            *(__half2*)&g_bufA[row1 * F + col] = h;
        }
    }
}

__device__ __forceinline__ void load_Wt_smem(__half* Wt, const __half* Wg) {
    int t = threadIdx.x;   // 128
    #pragma unroll
    for (int j = 0; j < 4; j++) {
        int idx = t + 128 * j;          // 512 uint4
        int n = idx >> 3, q = idx & 7;
        uint4 u = ((const uint4*)Wg)[idx];
        __half* p = &Wt[n * SA + q * 8];
        *(unsigned*)(p + 0) = u.x;
        *(unsigned*)(p + 2) = u.y;
        *(unsigned*)(p + 4) = u.z;
        *(unsigned*)(p + 6) = u.w;
    }
}

// ---------------- GEMM1: xs = (x @ W1) * dis -> fp16 bufA (HMMA) ------------
__global__ void k_gemm1(const float* __restrict__ x) {
    __shared__ __half As[64 * SA];
    __shared__ __half Wt[64 * SA];
    int t = threadIdx.x;
    int base = blockIdx.x * 64;
    load_Wt_smem(Wt, g_W1t);
    #pragma unroll
    for (int j = 0; j < 8; j++) {
        int idx = t + 128 * j;          // 1024 float4
        int r = idx >> 4, q = idx & 15;
        int row = base + r;
        float4 f = (row < N_NODES) ? ((const float4*)x)[(long long)row * 16 + q]
                                   : make_float4(0.f, 0.f, 0.f, 0.f);
        __half* p = &As[r * SA + q * 4];
        *(__half2*)(p + 0) = __floats2half2_rn(f.x, f.y);
        *(__half2*)(p + 2) = __floats2half2_rn(f.z, f.w);
    }
    __syncthreads();
    mma_body(As, Wt, base);
}

// ---------------- GEMM2: xs2 = (h @ W2) * dis -> fp16 bufA (HMMA) -----------
__global__ void k_gemm2() {
    __shared__ __half As[64 * SA];
    __shared__ __half Wt[64 * SA];
    int t = threadIdx.x;
    int base = blockIdx.x * 64;
    load_Wt_smem(Wt, g_W2t);
    #pragma unroll
    for (int j = 0; j < 4; j++) {
        int idx = t + 128 * j;          // 512 uint4
        int r = idx >> 3, q = idx & 7;
        int row = base + r;
        uint4 u = (row < N_NODES) ? ((const uint4*)g_bufH)[(long long)row * 8 + q]
                                  : make_uint4(0u, 0u, 0u, 0u);
        __half* p = &As[r * SA + q * 8];
        *(unsigned*)(p + 0) = u.x;
        *(unsigned*)(p + 2) = u.y;
        *(unsigned*)(p + 4) = u.z;
        *(unsigned*)(p + 6) = u.w;
    }
    __syncthreads();
    mma_body(As, Wt, base);
}

// ---------------- agg0 fused: h = relu(dis*(sum+xs)+b1) -> fp16 bufH ----------
__global__ void k_agg0(const float* __restrict__ b1) {
    int t = blockIdx.x * blockDim.x + threadIdx.x;
    int node = t >> 3;
    int lane = t & 7;
    if (node >= N_NODES) return;
    int beg = g_rowptr[node];
    int cnt = g_cnt[node];
    const uint4* A = (const uint4*)g_bufA;
    float acc[8] = {};
    int i = 0;
    for (; i + 4 <= cnt; i += 4) {
        int s0 = __ldg(&g_srcs[beg + i + 0]);
        int s1 = __ldg(&g_srcs[beg + i + 1]);
        int s2 = __ldg(&g_srcs[beg + i + 2]);
        int s3 = __ldg(&g_srcs[beg + i + 3]);
        uint4 u0 = __ldg(&A[s0 * 8 + lane]);
        uint4 u1 = __ldg(&A[s1 * 8 + lane]);
        uint4 u2 = __ldg(&A[s2 * 8 + lane]);
        uint4 u3 = __ldg(&A[s3 * 8 + lane]);
        acc_half8(acc, u0); acc_half8(acc, u1);
        acc_half8(acc, u2); acc_half8(acc, u3);
    }
    for (; i < cnt; i++) {
        int s = __ldg(&g_srcs[beg + i]);
        acc_half8(acc, __ldg(&A[s * 8 + lane]));
    }
    float dis = g_dis[node];
    float xs[8] = {};
    acc_half8(xs, __ldg(&A[node * 8 + lane]));
    uint4 out;
    float h0, h1;
    h0 = fmaxf(dis * (acc[0] + xs[0]) + b1[lane * 8 + 0], 0.0f);
    h1 = fmaxf(dis * (acc[1] + xs[1]) + b1[lane * 8 + 1], 0.0f);
    *(__half2*)&out.x = __floats2half2_rn(h0, h1);
    h0 = fmaxf(dis * (acc[2] + xs[2]) + b1[lane * 8 + 2], 0.0f);
    h1 = fmaxf(dis * (acc[3] + xs[3]) + b1[lane * 8 + 3], 0.0f);
    *(__half2*)&out.y = __floats2half2_rn(h0, h1);
    h0 = fmaxf(dis * (acc[4] + xs[4]) + b1[lane * 8 + 4], 0.0f);
    h1 = fmaxf(dis * (acc[5] + xs[5]) + b1[lane * 8 + 5], 0.0f);
    *(__half2*)&out.z = __floats2half2_rn(h0, h1);
    h0 = fmaxf(dis * (acc[6] + xs[6]) + b1[lane * 8 + 6], 0.0f);
    h1 = fmaxf(dis * (acc[7] + xs[7]) + b1[lane * 8 + 7], 0.0f);
    *(__half2*)&out.w = __floats2half2_rn(h0, h1);
    ((uint4*)g_bufH)[node * 8 + lane] = out;
}

// ---------------- agg1 fused with relu + mean-pool ----------------
__global__ void k_agg1(const float* __restrict__ b2, const int* __restrict__ batch) {
    __shared__ float hacc[32 * F];
    int tid = threadIdx.x;
    int s = tid >> 3;
    int lane = tid & 7;
    int base = blockIdx.x * 32;
    int node = base + s;
    int beg = g_rowptr[node];
    int cnt = g_cnt[node];
    const uint4* A = (const uint4*)g_bufA;
    float acc[8] = {};
    int i = 0;
    for (; i + 4 <= cnt; i += 4) {
        int s0 = __ldg(&g_srcs[beg + i + 0]);
        int s1 = __ldg(&g_srcs[beg + i + 1]);
        int s2 = __ldg(&g_srcs[beg + i + 2]);
        int s3 = __ldg(&g_srcs[beg + i + 3]);
        uint4 u0 = __ldg(&A[s0 * 8 + lane]);
        uint4 u1 = __ldg(&A[s1 * 8 + lane]);
        uint4 u2 = __ldg(&A[s2 * 8 + lane]);
        uint4 u3 = __ldg(&A[s3 * 8 + lane]);
        acc_half8(acc, u0); acc_half8(acc, u1);
        acc_half8(acc, u2); acc_half8(acc, u3);
    }
    for (; i < cnt; i++) {
        int sidx = __ldg(&g_srcs[beg + i]);
        acc_half8(acc, __ldg(&A[sidx * 8 + lane]));
    }
    float dis = g_dis[node];
    float xs[8] = {};
    acc_half8(xs, __ldg(&A[node * 8 + lane]));
    float h[8];
    #pragma unroll
    for (int j = 0; j < 8; j++)
        h[j] = fmaxf(dis * (acc[j] + xs[j]) + b2[lane * 8 + j], 0.0f);
    #pragma unroll
    for (int j = 0; j < 8; j++) hacc[s * F + lane * 8 + j] = h[j];
    __syncthreads();

    int g0 = batch[base];
    int g1 = batch[base + 31];
    if (g0 == g1) {
        #pragma unroll
        for (int off = 16; off >= 1; off >>= 1) {
            if (s < off) {
                #pragma unroll
                for (int j = 0; j < 8; j++)
                    hacc[s * F + lane * 8 + j] += hacc[(s + off) * F + lane * 8 + j];
            }
            __syncthreads();
        }
        if (tid < 16) {
            float4 v = ((float4*)hacc)[tid];
            red_v4(&g_gsum[g0 * F + tid * 4], v.x, v.y, v.z, v.w);
        }
    } else {
        int g = batch[node];
        red_v4(&g_gsum[g * F + lane * 8 + 0], h[0], h[1], h[2], h[3]);
        red_v4(&g_gsum[g * F + lane * 8 + 4], h[4], h[5], h[6], h[7]);
    }
}

// ---------------- head ----------------
__global__ void k_head(const float* __restrict__ topo, const float* __restrict__ Wlin,
                       const float* __restrict__ blin, float* __restrict__ out) {
    int t = threadIdx.x;
    int g = t >> 2, c = t & 3;
    float inv = 1.0f / fmaxf(g_gcnt[g], 1.0f);
    float acc = blin[c];
    #pragma unroll
    for (int k = 0; k < F; k++)
        acc = fmaf(g_gsum[g * F + k] * inv, Wlin[k * NUM_CLASSES + c], acc);
    #pragma unroll
    for (int k = 0; k < TOPO_DIM; k++)
        acc = fmaf(topo[g * TOPO_DIM + k], Wlin[(F + k) * NUM_CLASSES + c], acc);
    out[g * NUM_CLASSES + c] = acc;
}

extern "C" void kernel_launch(void* const* d_in, const int* in_sizes, int n_in,
                              void* d_out, int out_size) {
    const float* x    = (const float*)d_in[0];
    const int*   edge = (const int*)d_in[1];
    const int*   batch= (const int*)d_in[2];
    const float* topo = (const float*)d_in[3];
    const float* W1   = (const float*)d_in[4];
    const float* b1   = (const float*)d_in[5];
    const float* W2   = (const float*)d_in[6];
    const float* b2   = (const float*)d_in[7];
    const float* Wlin = (const float*)d_in[8];
    const float* blin = (const float*)d_in[9];
    float* out = (float*)d_out;

    const int gblocks = (N_NODES + 63) / 64;          // 1563
    const int ablocks = N_NODES * 8 / 256;            // 3125 exact
    const int eblocks = (N_EDGES / 4 + 255) / 256;    // 1563

    k_init<<<(N_NODES + 255) / 256, 256>>>();
    k_prepW<<<1, 256>>>(W1, W2);
    k_degree<<<eblocks, 256>>>(edge);
    k_scan1<<<SCAN_NBLK, SCAN_BLK>>>(batch);
    k_scan2<<<1, 256>>>();
    k_scan3<<<(N_NODES + 255) / 256, 256>>>();
    k_bin<<<eblocks, 256>>>(edge);
    k_gemm1<<<gblocks, 128>>>(x);
    k_agg0<<<ablocks, 256>>>(b1);
    k_gemm2<<<gblocks, 128>>>();
    k_agg1<<<ablocks, 256>>>(b2, batch);
    k_head<<<1, 256>>>(topo, Wlin, blin, out);
}

// round 12
// speedup vs baseline: 1.8413x; 1.0743x over previous
#include <cuda_runtime.h>
#include <cuda_fp16.h>

#define N_NODES 100000
#define N_EDGES 1600000
#define F 64
#define NUM_GRAPHS 64
#define TOPO_DIM 16
#define NUM_CLASSES 4

#define SCAN_BLK 512
#define SCAN_NBLK ((N_NODES + SCAN_BLK - 1) / SCAN_BLK)   // 196

#define SA 72   // smem row stride (halfs) — conflict-free for frag loads

// Scratch (device globals; allocation-free per harness rules)
__device__ int      g_cnt[N_NODES];       // zeroed at load + by k_scan3 each run
__device__ int      g_rowptr[N_NODES];
__device__ int      g_fill[N_NODES];      // after k_bin: fill[i] == rowptr[i]+cnt[i]
__device__ int      g_srcs[N_EDGES];
__device__ int      g_lscan[N_NODES];
__device__ int      g_bsum[SCAN_NBLK];
__device__ int      g_boff[SCAN_NBLK];
__device__ float    g_dis[N_NODES];
__device__ __half   g_bufA[N_NODES * F];   // xs (fp16) — gathered buffer
__device__ __half   g_bufH[N_NODES * F];   // h after layer1 relu (fp16)
__device__ __half   g_W1t[F * F];          // W1 transposed fp16 [n][k]
__device__ __half   g_W2t[F * F];          // W2 transposed fp16 [n][k]
__device__ float    g_gsum[NUM_GRAPHS * F];
__device__ float    g_gcnt[NUM_GRAPHS];

// ---------------- pre: degree histogram + zero gsum/gcnt + prep weights ------
__global__ void k_pre(const int* __restrict__ edge,
                      const float* __restrict__ W1, const float* __restrict__ W2) {
    int t = blockIdx.x * blockDim.x + threadIdx.x;
    if (t < NUM_GRAPHS * F) g_gsum[t] = 0.0f;
    if (t < NUM_GRAPHS) g_gcnt[t] = 0.0f;
    if (t >= 4096 && t < 8192) {           // weight transpose + fp16
        int e = t - 4096;
        int k = e >> 6, n = e & 63;
        g_W1t[n * F + k] = __float2half(W1[e]);
        g_W2t[n * F + k] = __float2half(W2[e]);
    }
    if (t < N_EDGES / 4) {
        int4 d = ((const int4*)(edge + N_EDGES))[t];
        atomicAdd(&g_cnt[d.x], 1);
        atomicAdd(&g_cnt[d.y], 1);
        atomicAdd(&g_cnt[d.z], 1);
        atomicAdd(&g_cnt[d.w], 1);
    }
}

// ---------------- 3-kernel prefix scan + dis + warp-aggregated gcnt ----------
__global__ void k_scan1(const int* __restrict__ batch) {
    __shared__ int s[SCAN_BLK];
    int t = threadIdx.x;
    int i = blockIdx.x * SCAN_BLK + t;
    int v = (i < N_NODES) ? g_cnt[i] : 0;
    if (i < N_NODES) {
        g_dis[i] = rsqrtf((float)v + 1.0f);
        int g = batch[i];
        unsigned active = __activemask();
        unsigned mask = __match_any_sync(active, g);
        int leader = __ffs(mask) - 1;
        if ((t & 31) == leader)
            atomicAdd(&g_gcnt[g], (float)__popc(mask));
    }
    s[t] = v;
    __syncthreads();
    #pragma unroll
    for (int off = 1; off < SCAN_BLK; off <<= 1) {
        int add = (t >= off) ? s[t - off] : 0;
        __syncthreads();
        s[t] += add;
        __syncthreads();
    }
    if (i < N_NODES) g_lscan[i] = s[t] - v;
    if (t == SCAN_BLK - 1) g_bsum[blockIdx.x] = s[t];
}

__global__ void k_scan2() {
    __shared__ int s[256];
    int t = threadIdx.x;
    int v = (t < SCAN_NBLK) ? g_bsum[t] : 0;
    s[t] = v;
    __syncthreads();
    #pragma unroll
    for (int off = 1; off < 256; off <<= 1) {
        int add = (t >= off) ? s[t - off] : 0;
        __syncthreads();
        s[t] += add;
        __syncthreads();
    }
    if (t < SCAN_NBLK) g_boff[t] = s[t] - v;
}

// scan3 also zeroes g_cnt (last read was in scan1) so next graph replay
// starts from a clean histogram.
__global__ void k_scan3() {
    int i = blockIdx.x * blockDim.x + threadIdx.x;
    if (i < N_NODES) {
        int rp = g_lscan[i] + g_boff[i / SCAN_BLK];
        g_rowptr[i] = rp;
        g_fill[i] = rp;
        g_cnt[i] = 0;
    }
}

// ---------------- bin edges by dst (4 edges/thread, MLP=4) ----------------
__global__ void k_bin(const int* __restrict__ edge) {
    int t = blockIdx.x * blockDim.x + threadIdx.x;
    if (t < N_EDGES / 4) {
        int4 s = ((const int4*)edge)[t];
        int4 d = ((const int4*)(edge + N_EDGES))[t];
        int p0 = atomicAdd(&g_fill[d.x], 1);
        int p1 = atomicAdd(&g_fill[d.y], 1);
        int p2 = atomicAdd(&g_fill[d.z], 1);
        int p3 = atomicAdd(&g_fill[d.w], 1);
        g_srcs[p0] = s.x;
        g_srcs[p1] = s.y;
        g_srcs[p2] = s.z;
        g_srcs[p3] = s.w;
    }
}

// ---------------- helpers ----------------
__device__ __forceinline__ void acc_half8(float* acc, uint4 u) {
    float2 f;
    f = __half22float2(*(__half2*)&u.x); acc[0] += f.x; acc[1] += f.y;
    f = __half22float2(*(__half2*)&u.y); acc[2] += f.x; acc[3] += f.y;
    f = __half22float2(*(__half2*)&u.z); acc[4] += f.x; acc[5] += f.y;
    f = __half22float2(*(__half2*)&u.w); acc[6] += f.x; acc[7] += f.y;
}

__device__ __forceinline__ void hacc4(__half2* hs, uint4 u) {
    hs[0] = __hadd2(hs[0], *(__half2*)&u.x);
    hs[1] = __hadd2(hs[1], *(__half2*)&u.y);
    hs[2] = __hadd2(hs[2], *(__half2*)&u.z);
    hs[3] = __hadd2(hs[3], *(__half2*)&u.w);
}

// CSR gather-sum for one (node, lane): fp16 HADD2 accumulation, flushed to
// fp32 every 8 edges to bound rounding error.
__device__ __forceinline__ void gather_sum(float* acc, int beg, int end, int lane) {
    const uint4* A = (const uint4*)g_bufA;
    int i = beg;
    while (i < end) {
        int stop = min(end, i + 8);
        __half2 hs[4];
        hs[0] = hs[1] = hs[2] = hs[3] = __float2half2_rn(0.0f);
        for (; i + 4 <= stop; i += 4) {
            int s0 = __ldg(&g_srcs[i + 0]);
            int s1 = __ldg(&g_srcs[i + 1]);
            int s2 = __ldg(&g_srcs[i + 2]);
            int s3 = __ldg(&g_srcs[i + 3]);
            uint4 u0 = __ldg(&A[s0 * 8 + lane]);
            uint4 u1 = __ldg(&A[s1 * 8 + lane]);
            uint4 u2 = __ldg(&A[s2 * 8 + lane]);
            uint4 u3 = __ldg(&A[s3 * 8 + lane]);
            hacc4(hs, u0); hacc4(hs, u1);
            hacc4(hs, u2); hacc4(hs, u3);
        }
        for (; i < stop; i++) {
            int s = __ldg(&g_srcs[i]);
            hacc4(hs, __ldg(&A[s * 8 + lane]));
        }
        float2 f;
        f = __half22float2(hs[0]); acc[0] += f.x; acc[1] += f.y;
        f = __half22float2(hs[1]); acc[2] += f.x; acc[3] += f.y;
        f = __half22float2(hs[2]); acc[4] += f.x; acc[5] += f.y;
        f = __half22float2(hs[3]); acc[6] += f.x; acc[7] += f.y;
    }
}

__device__ __forceinline__ void red_v4(float* p, float a, float b, float c, float d) {
    unsigned long long ga;
    asm("cvta.to.global.u64 %0, %1;" : "=l"(ga) : "l"(p));
    asm volatile("red.global.add.v4.f32 [%0], {%1,%2,%3,%4};"
                 :: "l"(ga), "f"(a), "f"(b), "f"(c), "f"(d) : "memory");
}

__device__ __forceinline__ void mma16816(float* c,
    unsigned a0, unsigned a1, unsigned a2, unsigned a3,
    unsigned b0, unsigned b1) {
    asm volatile("mma.sync.aligned.m16n8k16.row.col.f32.f16.f16.f32 "
        "{%0,%1,%2,%3}, {%4,%5,%6,%7}, {%8,%9}, {%0,%1,%2,%3};"
        : "+f"(c[0]), "+f"(c[1]), "+f"(c[2]), "+f"(c[3])
        : "r"(a0), "r"(a1), "r"(a2), "r"(a3), "r"(b0), "r"(b1));
}

// Shared mma mainloop + epilogue. Block = 128 threads (4 warps).
__device__ __forceinline__ void mma_body(const __half* As, const __half* Wt, int base) {
    int lane = threadIdx.x & 31;
    int w = threadIdx.x >> 5;
    int g = lane >> 2, tg = lane & 3;
    int R = w * 16;
    float c[8][4] = {};
    #pragma unroll
    for (int k0 = 0; k0 < F; k0 += 16) {
        unsigned a0 = *(const unsigned*)&As[(R + g) * SA + k0 + tg * 2];
        unsigned a1 = *(const unsigned*)&As[(R + g + 8) * SA + k0 + tg * 2];
        unsigned a2 = *(const unsigned*)&As[(R + g) * SA + k0 + tg * 2 + 8];
        unsigned a3 = *(const unsigned*)&As[(R + g + 8) * SA + k0 + tg * 2 + 8];
        #pragma unroll
        for (int n = 0; n < 8; n++) {
            unsigned b0 = *(const unsigned*)&Wt[(n * 8 + g) * SA + k0 + tg * 2];
            unsigned b1 = *(const unsigned*)&Wt[(n * 8 + g) * SA + k0 + tg * 2 + 8];
            mma16816(c[n], a0, a1, a2, a3, b0, b1);
        }
    }
    int row0 = base + R + g;
    int row1 = row0 + 8;
    float dis0 = (row0 < N_NODES) ? g_dis[row0] : 0.0f;
    float dis1 = (row1 < N_NODES) ? g_dis[row1] : 0.0f;
    #pragma unroll
    for (int n = 0; n < 8; n++) {
        int col = n * 8 + tg * 2;
        if (row0 < N_NODES) {
            __half2 h = __floats2half2_rn(c[n][0] * dis0, c[n][1] * dis0);
            *(__half2*)&g_bufA[row0 * F + col] = h;
        }
        if (row1 < N_NODES) {
            __half2 h = __floats2half2_rn(c[n][2] * dis1, c[n][3] * dis1);
            *(__half2*)&g_bufA[row1 * F + col] = h;
        }
    }
}

__device__ __forceinline__ void load_Wt_smem(__half* Wt, const __half* Wg) {
    int t = threadIdx.x;   // 128
    #pragma unroll
    for (int j = 0; j < 4; j++) {
        int idx = t + 128 * j;          // 512 uint4
        int n = idx >> 3, q = idx & 7;
        uint4 u = ((const uint4*)Wg)[idx];
        __half* p = &Wt[n * SA + q * 8];
        *(unsigned*)(p + 0) = u.x;
        *(unsigned*)(p + 2) = u.y;
        *(unsigned*)(p + 4) = u.z;
        *(unsigned*)(p + 6) = u.w;
    }
}

// ---------------- GEMM1: xs = (x @ W1) * dis -> fp16 bufA (HMMA) ------------
__global__ void k_gemm1(const float* __restrict__ x) {
    __shared__ __half As[64 * SA];
    __shared__ __half Wt[64 * SA];
    int t = threadIdx.x;
    int base = blockIdx.x * 64;
    load_Wt_smem(Wt, g_W1t);
    #pragma unroll
    for (int j = 0; j < 8; j++) {
        int idx = t + 128 * j;          // 1024 float4
        int r = idx >> 4, q = idx & 15;
        int row = base + r;
        float4 f = (row < N_NODES) ? ((const float4*)x)[(long long)row * 16 + q]
                                   : make_float4(0.f, 0.f, 0.f, 0.f);
        __half* p = &As[r * SA + q * 4];
        *(__half2*)(p + 0) = __floats2half2_rn(f.x, f.y);
        *(__half2*)(p + 2) = __floats2half2_rn(f.z, f.w);
    }
    __syncthreads();
    mma_body(As, Wt, base);
}

// ---------------- GEMM2: xs2 = (h @ W2) * dis -> fp16 bufA (HMMA) -----------
__global__ void k_gemm2() {
    __shared__ __half As[64 * SA];
    __shared__ __half Wt[64 * SA];
    int t = threadIdx.x;
    int base = blockIdx.x * 64;
    load_Wt_smem(Wt, g_W2t);
    #pragma unroll
    for (int j = 0; j < 4; j++) {
        int idx = t + 128 * j;          // 512 uint4
        int r = idx >> 3, q = idx & 7;
        int row = base + r;
        uint4 u = (row < N_NODES) ? ((const uint4*)g_bufH)[(long long)row * 8 + q]
                                  : make_uint4(0u, 0u, 0u, 0u);
        __half* p = &As[r * SA + q * 8];
        *(unsigned*)(p + 0) = u.x;
        *(unsigned*)(p + 2) = u.y;
        *(unsigned*)(p + 4) = u.z;
        *(unsigned*)(p + 6) = u.w;
    }
    __syncthreads();
    mma_body(As, Wt, base);
}

// ---------------- agg0 fused: h = relu(dis*(sum+xs)+b1) -> fp16 bufH ----------
__global__ void k_agg0(const float* __restrict__ b1) {
    int t = blockIdx.x * blockDim.x + threadIdx.x;
    int node = t >> 3;
    int lane = t & 7;
    if (node >= N_NODES) return;
    int beg = g_rowptr[node];
    int end = g_fill[node];
    float acc[8] = {};
    gather_sum(acc, beg, end, lane);
    float dis = g_dis[node];
    float xs[8] = {};
    acc_half8(xs, __ldg(&((const uint4*)g_bufA)[node * 8 + lane]));
    uint4 out;
    float h0, h1;
    h0 = fmaxf(dis * (acc[0] + xs[0]) + b1[lane * 8 + 0], 0.0f);
    h1 = fmaxf(dis * (acc[1] + xs[1]) + b1[lane * 8 + 1], 0.0f);
    *(__half2*)&out.x = __floats2half2_rn(h0, h1);
    h0 = fmaxf(dis * (acc[2] + xs[2]) + b1[lane * 8 + 2], 0.0f);
    h1 = fmaxf(dis * (acc[3] + xs[3]) + b1[lane * 8 + 3], 0.0f);
    *(__half2*)&out.y = __floats2half2_rn(h0, h1);
    h0 = fmaxf(dis * (acc[4] + xs[4]) + b1[lane * 8 + 4], 0.0f);
    h1 = fmaxf(dis * (acc[5] + xs[5]) + b1[lane * 8 + 5], 0.0f);
    *(__half2*)&out.z = __floats2half2_rn(h0, h1);
    h0 = fmaxf(dis * (acc[6] + xs[6]) + b1[lane * 8 + 6], 0.0f);
    h1 = fmaxf(dis * (acc[7] + xs[7]) + b1[lane * 8 + 7], 0.0f);
    *(__half2*)&out.w = __floats2half2_rn(h0, h1);
    ((uint4*)g_bufH)[node * 8 + lane] = out;
}

// ---------------- agg1 fused with relu + mean-pool ----------------
__global__ void k_agg1(const float* __restrict__ b2, const int* __restrict__ batch) {
    __shared__ float hacc[32 * F];
    int tid = threadIdx.x;
    int s = tid >> 3;
    int lane = tid & 7;
    int base = blockIdx.x * 32;
    int node = base + s;
    int beg = g_rowptr[node];
    int end = g_fill[node];
    float acc[8] = {};
    gather_sum(acc, beg, end, lane);
    float dis = g_dis[node];
    float xs[8] = {};
    acc_half8(xs, __ldg(&((const uint4*)g_bufA)[node * 8 + lane]));
    float h[8];
    #pragma unroll
    for (int j = 0; j < 8; j++)
        h[j] = fmaxf(dis * (acc[j] + xs[j]) + b2[lane * 8 + j], 0.0f);
    #pragma unroll
    for (int j = 0; j < 8; j++) hacc[s * F + lane * 8 + j] = h[j];
    __syncthreads();

    int g0 = batch[base];
    int g1 = batch[base + 31];
    if (g0 == g1) {
        #pragma unroll
        for (int off = 16; off >= 1; off >>= 1) {
            if (s < off) {
                #pragma unroll
                for (int j = 0; j < 8; j++)
                    hacc[s * F + lane * 8 + j] += hacc[(s + off) * F + lane * 8 + j];
            }
            __syncthreads();
        }
        if (tid < 16) {
            float4 v = ((float4*)hacc)[tid];
            red_v4(&g_gsum[g0 * F + tid * 4], v.x, v.y, v.z, v.w);
        }
    } else {
        int g = batch[node];
        red_v4(&g_gsum[g * F + lane * 8 + 0], h[0], h[1], h[2], h[3]);
        red_v4(&g_gsum[g * F + lane * 8 + 4], h[4], h[5], h[6], h[7]);
    }
}

// ---------------- head ----------------
__global__ void k_head(const float* __restrict__ topo, const float* __restrict__ Wlin,
                       const float* __restrict__ blin, float* __restrict__ out) {
    int t = threadIdx.x;
    int g = t >> 2, c = t & 3;
    float inv = 1.0f / fmaxf(g_gcnt[g], 1.0f);
    float acc = blin[c];
    #pragma unroll
    for (int k = 0; k < F; k++)
        acc = fmaf(g_gsum[g * F + k] * inv, Wlin[k * NUM_CLASSES + c], acc);
    #pragma unroll
    for (int k = 0; k < TOPO_DIM; k++)
        acc = fmaf(topo[g * TOPO_DIM + k], Wlin[(F + k) * NUM_CLASSES + c], acc);
    out[g * NUM_CLASSES + c] = acc;
}

extern "C" void kernel_launch(void* const* d_in, const int* in_sizes, int n_in,
                              void* d_out, int out_size) {
    const float* x    = (const float*)d_in[0];
    const int*   edge = (const int*)d_in[1];
    const int*   batch= (const int*)d_in[2];
    const float* topo = (const float*)d_in[3];
    const float* W1   = (const float*)d_in[4];
    const float* b1   = (const float*)d_in[5];
    const float* W2   = (const float*)d_in[6];
    const float* b2   = (const float*)d_in[7];
    const float* Wlin = (const float*)d_in[8];
    const float* blin = (const float*)d_in[9];
    float* out = (float*)d_out;

    const int gblocks = (N_NODES + 63) / 64;          // 1563
    const int ablocks = N_NODES * 8 / 256;            // 3125 exact
    const int eblocks = (N_EDGES / 4 + 255) / 256;    // 1563

    k_pre<<<eblocks, 256>>>(edge, W1, W2);
    k_scan1<<<SCAN_NBLK, SCAN_BLK>>>(batch);
    k_scan2<<<1, 256>>>();
    k_scan3<<<(N_NODES + 255) / 256, 256>>>();
    k_bin<<<eblocks, 256>>>(edge);
    k_gemm1<<<gblocks, 128>>>(x);
    k_agg0<<<ablocks, 256>>>(b1);
    k_gemm2<<<gblocks, 128>>>();
    k_agg1<<<ablocks, 256>>>(b2, batch);
    k_head<<<1, 256>>>(topo, Wlin, blin, out);
}

// round 13
// speedup vs baseline: 1.9032x; 1.0336x over previous
#include <cuda_runtime.h>
#include <cuda_fp16.h>

#define N_NODES 100000
#define N_EDGES 1600000
#define F 64
#define NUM_GRAPHS 64
#define TOPO_DIM 16
#define NUM_CLASSES 4

#define SCAN_BLK 512
#define SCAN_NBLK ((N_NODES + SCAN_BLK - 1) / SCAN_BLK)   // 196

#define SA 72   // smem row stride (halfs) — conflict-free for frag loads

// Scratch (device globals; allocation-free per harness rules)
__device__ int      g_cnt[N_NODES];       // zeroed at load + by k_scan3 each run
__device__ int      g_rowptr[N_NODES];
__device__ int      g_fill[N_NODES];      // after k_bin: fill[i] == rowptr[i]+cnt[i]
__device__ int      g_srcs[N_EDGES];
__device__ int      g_lscan[N_NODES];
__device__ int      g_bsum[SCAN_NBLK];
__device__ float    g_dis[N_NODES];
__device__ __half   g_bufA[N_NODES * F];   // xs (fp16) — gathered buffer
__device__ __half   g_bufH[N_NODES * F];   // h after layer1 relu (fp16)
__device__ __half   g_W1t[F * F];          // W1 transposed fp16 [n][k]
__device__ __half   g_W2t[F * F];          // W2 transposed fp16 [n][k]
__device__ float    g_gsum[NUM_GRAPHS * F];
__device__ float    g_gcnt[NUM_GRAPHS];

// ---------------- pre: degree histogram + zero gsum/gcnt + prep weights ------
__global__ void k_pre(const int* __restrict__ edge,
                      const float* __restrict__ W1, const float* __restrict__ W2) {
    int t = blockIdx.x * blockDim.x + threadIdx.x;
    if (t < NUM_GRAPHS * F) g_gsum[t] = 0.0f;
    if (t < NUM_GRAPHS) g_gcnt[t] = 0.0f;
    if (t >= 4096 && t < 8192) {           // weight transpose + fp16
        int e = t - 4096;
        int k = e >> 6, n = e & 63;
        g_W1t[n * F + k] = __float2half(W1[e]);
        g_W2t[n * F + k] = __float2half(W2[e]);
    }
    if (t < N_EDGES / 4) {
        int4 d = ((const int4*)(edge + N_EDGES))[t];
        atomicAdd(&g_cnt[d.x], 1);
        atomicAdd(&g_cnt[d.y], 1);
        atomicAdd(&g_cnt[d.z], 1);
        atomicAdd(&g_cnt[d.w], 1);
    }
}

// ---------------- scan1: block-local scan + dis + warp-aggregated gcnt -------
__global__ void k_scan1(const int* __restrict__ batch) {
    __shared__ int s[SCAN_BLK];
    int t = threadIdx.x;
    int i = blockIdx.x * SCAN_BLK + t;
    int v = (i < N_NODES) ? g_cnt[i] : 0;
    if (i < N_NODES) {
        g_dis[i] = rsqrtf((float)v + 1.0f);
        int g = batch[i];
        unsigned active = __activemask();
        unsigned mask = __match_any_sync(active, g);
        int leader = __ffs(mask) - 1;
        if ((t & 31) == leader)
            atomicAdd(&g_gcnt[g], (float)__popc(mask));
    }
    s[t] = v;
    __syncthreads();
    #pragma unroll
    for (int off = 1; off < SCAN_BLK; off <<= 1) {
        int add = (t >= off) ? s[t - off] : 0;
        __syncthreads();
        s[t] += add;
        __syncthreads();
    }
    if (i < N_NODES) g_lscan[i] = s[t] - v;
    if (t == SCAN_BLK - 1) g_bsum[blockIdx.x] = s[t];
}

// scan3 (scan2 folded in): each 256-node block lies in exactly one 512-wide
// scan block (sb = blockIdx>>1); warp 0 sums g_bsum[0..sb) itself.
// Also zeroes g_cnt for the next graph replay.
__global__ void k_scan3() {
    __shared__ int s_boff;
    int b = blockIdx.x;
    int t = threadIdx.x;
    int sb = b >> 1;
    if (t < 32) {
        int sum = 0;
        for (int base = 0; base < sb; base += 32) {
            int idx = base + t;
            sum += (idx < sb) ? g_bsum[idx] : 0;
        }
        #pragma unroll
        for (int off = 16; off; off >>= 1)
            sum += __shfl_down_sync(0xffffffffu, sum, off);
        if (t == 0) s_boff = sum;
    }
    __syncthreads();
    int i = b * 256 + t;
    if (i < N_NODES) {
        int rp = g_lscan[i] + s_boff;
        g_rowptr[i] = rp;
        g_fill[i] = rp;
        g_cnt[i] = 0;
    }
}

// ---------------- bin edges by dst (4 edges/thread, MLP=4) ----------------
__global__ void k_bin(const int* __restrict__ edge) {
    int t = blockIdx.x * blockDim.x + threadIdx.x;
    if (t < N_EDGES / 4) {
        int4 s = ((const int4*)edge)[t];
        int4 d = ((const int4*)(edge + N_EDGES))[t];
        int p0 = atomicAdd(&g_fill[d.x], 1);
        int p1 = atomicAdd(&g_fill[d.y], 1);
        int p2 = atomicAdd(&g_fill[d.z], 1);
        int p3 = atomicAdd(&g_fill[d.w], 1);
        g_srcs[p0] = s.x;
        g_srcs[p1] = s.y;
        g_srcs[p2] = s.z;
        g_srcs[p3] = s.w;
    }
}

// ---------------- helpers ----------------
__device__ __forceinline__ void acc_half8(float* acc, uint4 u) {
    float2 f;
    f = __half22float2(*(__half2*)&u.x); acc[0] += f.x; acc[1] += f.y;
    f = __half22float2(*(__half2*)&u.y); acc[2] += f.x; acc[3] += f.y;
    f = __half22float2(*(__half2*)&u.z); acc[4] += f.x; acc[5] += f.y;
    f = __half22float2(*(__half2*)&u.w); acc[6] += f.x; acc[7] += f.y;
}

__device__ __forceinline__ void hacc4(__half2* hs, uint4 u) {
    hs[0] = __hadd2(hs[0], *(__half2*)&u.x);
    hs[1] = __hadd2(hs[1], *(__half2*)&u.y);
    hs[2] = __hadd2(hs[2], *(__half2*)&u.z);
    hs[3] = __hadd2(hs[3], *(__half2*)&u.w);
}

// CSR gather-sum: fp16 HADD2 accumulation in 8-edge windows (flushed to fp32),
// all 8 src loads + 8 row gathers issued as independent loads (MLP=8).
__device__ __forceinline__ void gather_sum(float* acc, int beg, int end, int lane) {
    const uint4* A = (const uint4*)g_bufA;
    int i = beg;
    while (i < end) {
        __half2 hs[4];
        hs[0] = hs[1] = hs[2] = hs[3] = __float2half2_rn(0.0f);
        if (end - i >= 8) {
            int s[8];
            #pragma unroll
            for (int j = 0; j < 8; j++) s[j] = __ldg(&g_srcs[i + j]);
            uint4 u[8];
            #pragma unroll
            for (int j = 0; j < 8; j++) u[j] = __ldg(&A[s[j] * 8 + lane]);
            #pragma unroll
            for (int j = 0; j < 8; j++) hacc4(hs, u[j]);
            i += 8;
        } else {
            for (; i < end; i++) {
                int s = __ldg(&g_srcs[i]);
                hacc4(hs, __ldg(&A[s * 8 + lane]));
            }
        }
        float2 f;
        f = __half22float2(hs[0]); acc[0] += f.x; acc[1] += f.y;
        f = __half22float2(hs[1]); acc[2] += f.x; acc[3] += f.y;
        f = __half22float2(hs[2]); acc[4] += f.x; acc[5] += f.y;
        f = __half22float2(hs[3]); acc[6] += f.x; acc[7] += f.y;
    }
}

__device__ __forceinline__ void red_v4(float* p, float a, float b, float c, float d) {
    unsigned long long ga;
    asm("cvta.to.global.u64 %0, %1;" : "=l"(ga) : "l"(p));
    asm volatile("red.global.add.v4.f32 [%0], {%1,%2,%3,%4};"
                 :: "l"(ga), "f"(a), "f"(b), "f"(c), "f"(d) : "memory");
}

__device__ __forceinline__ void mma16816(float* c,
    unsigned a0, unsigned a1, unsigned a2, unsigned a3,
    unsigned b0, unsigned b1) {
    asm volatile("mma.sync.aligned.m16n8k16.row.col.f32.f16.f16.f32 "
        "{%0,%1,%2,%3}, {%4,%5,%6,%7}, {%8,%9}, {%0,%1,%2,%3};"
        : "+f"(c[0]), "+f"(c[1]), "+f"(c[2]), "+f"(c[3])
        : "r"(a0), "r"(a1), "r"(a2), "r"(a3), "r"(b0), "r"(b1));
}

// Shared mma mainloop + epilogue. Block = 128 threads (4 warps).
__device__ __forceinline__ void mma_body(const __half* As, const __half* Wt, int base) {
    int lane = threadIdx.x & 31;
    int w = threadIdx.x >> 5;
    int g = lane >> 2, tg = lane & 3;
    int R = w * 16;
    float c[8][4] = {};
    #pragma unroll
    for (int k0 = 0; k0 < F; k0 += 16) {
        unsigned a0 = *(const unsigned*)&As[(R + g) * SA + k0 + tg * 2];
        unsigned a1 = *(const unsigned*)&As[(R + g + 8) * SA + k0 + tg * 2];
        unsigned a2 = *(const unsigned*)&As[(R + g) * SA + k0 + tg * 2 + 8];
        unsigned a3 = *(const unsigned*)&As[(R + g + 8) * SA + k0 + tg * 2 + 8];
        #pragma unroll
        for (int n = 0; n < 8; n++) {
            unsigned b0 = *(const unsigned*)&Wt[(n * 8 + g) * SA + k0 + tg * 2];
            unsigned b1 = *(const unsigned*)&Wt[(n * 8 + g) * SA + k0 + tg * 2 + 8];
            mma16816(c[n], a0, a1, a2, a3, b0, b1);
        }
    }
    int row0 = base + R + g;
    int row1 = row0 + 8;
    float dis0 = (row0 < N_NODES) ? g_dis[row0] : 0.0f;
    float dis1 = (row1 < N_NODES) ? g_dis[row1] : 0.0f;
    #pragma unroll
    for (int n = 0; n < 8; n++) {
        int col = n * 8 + tg * 2;
        if (row0 < N_NODES) {
            __half2 h = __floats2half2_rn(c[n][0] * dis0, c[n][1] * dis0);
            *(__half2*)&g_bufA[row0 * F + col] = h;
        }
        if (row1 < N_NODES) {
            __half2 h = __floats2half2_rn(c[n][2] * dis1, c[n][3] * dis1);
            *(__half2*)&g_bufA[row1 * F + col] = h;
        }
    }
}

__device__ __forceinline__ void load_Wt_smem(__half* Wt, const __half* Wg) {
    int t = threadIdx.x;   // 128
    #pragma unroll
    for (int j = 0; j < 4; j++) {
        int idx = t + 128 * j;          // 512 uint4
        int n = idx >> 3, q = idx & 7;
        uint4 u = ((const uint4*)Wg)[idx];
        __half* p = &Wt[n * SA + q * 8];
        *(unsigned*)(p + 0) = u.x;
        *(unsigned*)(p + 2) = u.y;
        *(unsigned*)(p + 4) = u.z;
        *(unsigned*)(p + 6) = u.w;
    }
}

// ---------------- GEMM1: xs = (x @ W1) * dis -> fp16 bufA (HMMA) ------------
__global__ void k_gemm1(const float* __restrict__ x) {
    __shared__ __half As[64 * SA];
    __shared__ __half Wt[64 * SA];
    int t = threadIdx.x;
    int base = blockIdx.x * 64;
    load_Wt_smem(Wt, g_W1t);
    #pragma unroll
    for (int j = 0; j < 8; j++) {
        int idx = t + 128 * j;          // 1024 float4
        int r = idx >> 4, q = idx & 15;
        int row = base + r;
        float4 f = (row < N_NODES) ? ((const float4*)x)[(long long)row * 16 + q]
                                   : make_float4(0.f, 0.f, 0.f, 0.f);
        __half* p = &As[r * SA + q * 4];
        *(__half2*)(p + 0) = __floats2half2_rn(f.x, f.y);
        *(__half2*)(p + 2) = __floats2half2_rn(f.z, f.w);
    }
    __syncthreads();
    mma_body(As, Wt, base);
}

// ---------------- GEMM2: xs2 = (h @ W2) * dis -> fp16 bufA (HMMA) -----------
__global__ void k_gemm2() {
    __shared__ __half As[64 * SA];
    __shared__ __half Wt[64 * SA];
    int t = threadIdx.x;
    int base = blockIdx.x * 64;
    load_Wt_smem(Wt, g_W2t);
    #pragma unroll
    for (int j = 0; j < 4; j++) {
        int idx = t + 128 * j;          // 512 uint4
        int r = idx >> 3, q = idx & 7;
        int row = base + r;
        uint4 u = (row < N_NODES) ? ((const uint4*)g_bufH)[(long long)row * 8 + q]
                                  : make_uint4(0u, 0u, 0u, 0u);
        __half* p = &As[r * SA + q * 8];
        *(unsigned*)(p + 0) = u.x;
        *(unsigned*)(p + 2) = u.y;
        *(unsigned*)(p + 4) = u.z;
        *(unsigned*)(p + 6) = u.w;
    }
    __syncthreads();
    mma_body(As, Wt, base);
}

// ---------------- agg0 fused: h = relu(dis*(sum+xs)+b1) -> fp16 bufH ----------
__global__ void k_agg0(const float* __restrict__ b1) {
    int t = blockIdx.x * blockDim.x + threadIdx.x;
    int node = t >> 3;
    int lane = t & 7;
    if (node >= N_NODES) return;
    int beg = g_rowptr[node];
    int end = g_fill[node];
    float acc[8] = {};
    gather_sum(acc, beg, end, lane);
    float dis = g_dis[node];
    float xs[8] = {};
    acc_half8(xs, __ldg(&((const uint4*)g_bufA)[node * 8 + lane]));
    uint4 out;
    float h0, h1;
    h0 = fmaxf(dis * (acc[0] + xs[0]) + b1[lane * 8 + 0], 0.0f);
    h1 = fmaxf(dis * (acc[1] + xs[1]) + b1[lane * 8 + 1], 0.0f);
    *(__half2*)&out.x = __floats2half2_rn(h0, h1);
    h0 = fmaxf(dis * (acc[2] + xs[2]) + b1[lane * 8 + 2], 0.0f);
    h1 = fmaxf(dis * (acc[3] + xs[3]) + b1[lane * 8 + 3], 0.0f);
    *(__half2*)&out.y = __floats2half2_rn(h0, h1);
    h0 = fmaxf(dis * (acc[4] + xs[4]) + b1[lane * 8 + 4], 0.0f);
    h1 = fmaxf(dis * (acc[5] + xs[5]) + b1[lane * 8 + 5], 0.0f);
    *(__half2*)&out.z = __floats2half2_rn(h0, h1);
    h0 = fmaxf(dis * (acc[6] + xs[6]) + b1[lane * 8 + 6], 0.0f);
    h1 = fmaxf(dis * (acc[7] + xs[7]) + b1[lane * 8 + 7], 0.0f);
    *(__half2*)&out.w = __floats2half2_rn(h0, h1);
    ((uint4*)g_bufH)[node * 8 + lane] = out;
}

// ---------------- agg1 fused with relu + mean-pool ----------------
__global__ void k_agg1(const float* __restrict__ b2, const int* __restrict__ batch) {
    __shared__ float hacc[32 * F];
    int tid = threadIdx.x;
    int s = tid >> 3;
    int lane = tid & 7;
    int base = blockIdx.x * 32;
    int node = base + s;
    int beg = g_rowptr[node];
    int end = g_fill[node];
    float acc[8] = {};
    gather_sum(acc, beg, end, lane);
    float dis = g_dis[node];
    float xs[8] = {};
    acc_half8(xs, __ldg(&((const uint4*)g_bufA)[node * 8 + lane]));
    float h[8];
    #pragma unroll
    for (int j = 0; j < 8; j++)
        h[j] = fmaxf(dis * (acc[j] + xs[j]) + b2[lane * 8 + j], 0.0f);
    #pragma unroll
    for (int j = 0; j < 8; j++) hacc[s * F + lane * 8 + j] = h[j];
    __syncthreads();

    int g0 = batch[base];
    int g1 = batch[base + 31];
    if (g0 == g1) {
        #pragma unroll
        for (int off = 16; off >= 1; off >>= 1) {
            if (s < off) {
                #pragma unroll
                for (int j = 0; j < 8; j++)
                    hacc[s * F + lane * 8 + j] += hacc[(s + off) * F + lane * 8 + j];
            }
            __syncthreads();
        }
        if (tid < 16) {
            float4 v = ((float4*)hacc)[tid];
            red_v4(&g_gsum[g0 * F + tid * 4], v.x, v.y, v.z, v.w);
        }
    } else {
        int g = batch[node];
        red_v4(&g_gsum[g * F + lane * 8 + 0], h[0], h[1], h[2], h[3]);
        red_v4(&g_gsum[g * F + lane * 8 + 4], h[4], h[5], h[6], h[7]);
    }
}

// ---------------- head ----------------
__global__ void k_head(const float* __restrict__ topo, const float* __restrict__ Wlin,
                       const float* __restrict__ blin, float* __restrict__ out) {
    int t = threadIdx.x;
    int g = t >> 2, c = t & 3;
    float inv = 1.0f / fmaxf(g_gcnt[g], 1.0f);
    float acc = blin[c];
    #pragma unroll
    for (int k = 0; k < F; k++)
        acc = fmaf(g_gsum[g * F + k] * inv, Wlin[k * NUM_CLASSES + c], acc);
    #pragma unroll
    for (int k = 0; k < TOPO_DIM; k++)
        acc = fmaf(topo[g * TOPO_DIM + k], Wlin[(F + k) * NUM_CLASSES + c], acc);
    out[g * NUM_CLASSES + c] = acc;
}

extern "C" void kernel_launch(void* const* d_in, const int* in_sizes, int n_in,
                              void* d_out, int out_size) {
    const float* x    = (const float*)d_in[0];
    const int*   edge = (const int*)d_in[1];
    const int*   batch= (const int*)d_in[2];
    const float* topo = (const float*)d_in[3];
    const float* W1   = (const float*)d_in[4];
    const float* b1   = (const float*)d_in[5];
    const float* W2   = (const float*)d_in[6];
    const float* b2   = (const float*)d_in[7];
    const float* Wlin = (const float*)d_in[8];
    const float* blin = (const float*)d_in[9];
    float* out = (float*)d_out;

    const int gblocks = (N_NODES + 63) / 64;          // 1563
    const int ablocks = N_NODES * 8 / 256;            // 3125 exact
    const int eblocks = (N_EDGES / 4 + 255) / 256;    // 1563

    k_pre<<<eblocks, 256>>>(edge, W1, W2);
    k_scan1<<<SCAN_NBLK, SCAN_BLK>>>(batch);
    k_scan3<<<(N_NODES + 255) / 256, 256>>>();
    k_bin<<<eblocks, 256>>>(edge);
    k_gemm1<<<gblocks, 128>>>(x);
    k_agg0<<<ablocks, 256>>>(b1);
    k_gemm2<<<gblocks, 128>>>();
    k_agg1<<<ablocks, 256>>>(b2, batch);
    k_head<<<1, 256>>>(topo, Wlin, blin, out);
}